// round 1
// baseline (speedup 1.0000x reference)
#include <cuda_runtime.h>
#include <math.h>

#define SEQ    8192
#define HIDDIM 768
#define NHEAD  12
#define HD     64
#define WIN    256

// Scratch (allocation-free rule: __device__ globals)
__device__ float g_Q[SEQ * HIDDIM];
__device__ float g_K[SEQ * HIDDIM];
__device__ float g_V[SEQ * HIDDIM];

// ---------------------------------------------------------------------------
// C[M,N] = (A[M,K] @ W[K,N] + bias[N]) * scale
// M=8192, N=768, K=768.  BM=BN=128, BK=8, 256 threads, 8x8 microtile.
// Grid: (N/128=6, M/128=64). All dims divide exactly -> no guards.
// ---------------------------------------------------------------------------
__global__ __launch_bounds__(256) void qkv_gemm(
    const float* __restrict__ A, const float* __restrict__ W,
    const float* __restrict__ bias, float* __restrict__ C, float scale)
{
    __shared__ float As[8][128];   // transposed A tile: As[k][m]
    __shared__ float Bs[8][128];   // Bs[k][n]

    const int m0 = blockIdx.y * 128;
    const int n0 = blockIdx.x * 128;
    const int t  = threadIdx.x;
    const int ty = t >> 4;         // 0..15 -> m frag = ty*8
    const int tx = t & 15;         // 0..15 -> n frag = tx*8

    const int arow = t >> 1;           // 0..127
    const int acol = (t & 1) << 2;     // 0 or 4
    const int brow = t >> 5;           // 0..7
    const int bcol = (t & 31) << 2;    // 0..124

    const float* aptr = A + (size_t)(m0 + arow) * HIDDIM + acol;
    const float* bptr = W + (size_t)brow * HIDDIM + n0 + bcol;

    float acc[8][8];
    #pragma unroll
    for (int i = 0; i < 8; i++)
        #pragma unroll
        for (int j = 0; j < 8; j++) acc[i][j] = 0.f;

    for (int k0 = 0; k0 < HIDDIM; k0 += 8) {
        float4 av = *(const float4*)(aptr + k0);
        float4 bv = *(const float4*)(bptr + (size_t)k0 * HIDDIM);
        __syncthreads();
        As[acol + 0][arow] = av.x;
        As[acol + 1][arow] = av.y;
        As[acol + 2][arow] = av.z;
        As[acol + 3][arow] = av.w;
        *(float4*)&Bs[brow][bcol] = bv;
        __syncthreads();
        #pragma unroll
        for (int kk = 0; kk < 8; kk++) {
            float a[8], b[8];
            *(float4*)(a)     = *(const float4*)&As[kk][ty * 8];
            *(float4*)(a + 4) = *(const float4*)&As[kk][ty * 8 + 4];
            *(float4*)(b)     = *(const float4*)&Bs[kk][tx * 8];
            *(float4*)(b + 4) = *(const float4*)&Bs[kk][tx * 8 + 4];
            #pragma unroll
            for (int i = 0; i < 8; i++)
                #pragma unroll
                for (int j = 0; j < 8; j++)
                    acc[i][j] = fmaf(a[i], b[j], acc[i][j]);
        }
    }

    #pragma unroll
    for (int i = 0; i < 8; i++) {
        const int row = m0 + ty * 8 + i;
        float* cp = C + (size_t)row * HIDDIM + n0 + tx * 8;
        #pragma unroll
        for (int j = 0; j < 8; j++)
            cp[j] = (acc[i][j] + bias[n0 + tx * 8 + j]) * scale;
    }
}

// ---------------------------------------------------------------------------
// Sliding-window flash attention.
// Block = (64-query tile, head). 9 key tiles of 64 cover [q0-256, q0+320).
// 256 threads, 4x4 microtiles. Online softmax; P staged via smem for PV.
// ---------------------------------------------------------------------------
__global__ __launch_bounds__(256) void swa_attn(float* __restrict__ out)
{
    extern __shared__ float sm[];
    float* Qs = sm;                // [64][65]
    float* Ks = sm + 64 * 65;      // [64][65]
    float* Vs = sm + 2 * 64 * 65;  // [64][65]
    float* Ps = sm + 3 * 64 * 65;  // [64][65]

    const int q0 = blockIdx.x * 64;
    const int h  = blockIdx.y;
    const int t  = threadIdx.x;
    const int ty = t >> 4;         // 0..15
    const int tx = t & 15;         // 0..15
    const int r0 = ty << 2;        // query-row frag
    const int c0 = tx << 2;        // key-col frag / out-dim frag

    // Load Q tile (64 rows x 64 dims), 4 threads per row, 4 float4 each
    {
        const int row = t >> 2;
        const int seg = (t & 3) << 4;
        const float* src = g_Q + (size_t)(q0 + row) * HIDDIM + h * HD + seg;
        #pragma unroll
        for (int i = 0; i < 4; i++) {
            float4 v = *(const float4*)(src + i * 4);
            float* d = Qs + row * 65 + seg + i * 4;
            d[0] = v.x; d[1] = v.y; d[2] = v.z; d[3] = v.w;
        }
    }

    float m_run[4], l_run[4], oacc[4][4];
    #pragma unroll
    for (int i = 0; i < 4; i++) {
        m_run[i] = -INFINITY; l_run[i] = 0.f;
        #pragma unroll
        for (int j = 0; j < 4; j++) oacc[i][j] = 0.f;
    }

    for (int kt = 0; kt < 9; kt++) {
        const int kbase = q0 - WIN + kt * 64;

        __syncthreads();   // prev PV done before K/V overwrite
        {
            const int row  = t >> 2;
            const int seg  = (t & 3) << 4;
            const int krow = kbase + row;
            const bool ok  = (krow >= 0) && (krow < SEQ);
            const size_t off = (size_t)(ok ? krow : 0) * HIDDIM + h * HD + seg;
            const float* ksrc = g_K + off;
            const float* vsrc = g_V + off;
            #pragma unroll
            for (int i = 0; i < 4; i++) {
                float4 kv = ok ? *(const float4*)(ksrc + i * 4) : make_float4(0, 0, 0, 0);
                float4 vv = ok ? *(const float4*)(vsrc + i * 4) : make_float4(0, 0, 0, 0);
                float* kd = Ks + row * 65 + seg + i * 4;
                kd[0] = kv.x; kd[1] = kv.y; kd[2] = kv.z; kd[3] = kv.w;
                float* vd = Vs + row * 65 + seg + i * 4;
                vd[0] = vv.x; vd[1] = vv.y; vd[2] = vv.z; vd[3] = vv.w;
            }
        }
        __syncthreads();

        // S = Q . K^T  (4x4 microtile over 64-dim reduction)
        float s[4][4];
        #pragma unroll
        for (int i = 0; i < 4; i++)
            #pragma unroll
            for (int j = 0; j < 4; j++) s[i][j] = 0.f;

        #pragma unroll 8
        for (int kk = 0; kk < 64; kk++) {
            float a[4], b[4];
            #pragma unroll
            for (int i = 0; i < 4; i++) a[i] = Qs[(r0 + i) * 65 + kk];
            #pragma unroll
            for (int j = 0; j < 4; j++) b[j] = Ks[(c0 + j) * 65 + kk];
            #pragma unroll
            for (int i = 0; i < 4; i++)
                #pragma unroll
                for (int j = 0; j < 4; j++)
                    s[i][j] = fmaf(a[i], b[j], s[i][j]);
        }

        // Mask + online softmax update (per query row)
        #pragma unroll
        for (int i = 0; i < 4; i++) {
            const int qpos = q0 + r0 + i;
            bool vm[4];
            float rowm = -1e30f;
            #pragma unroll
            for (int j = 0; j < 4; j++) {
                const int kpos = kbase + c0 + j;
                vm[j] = (kpos >= 0) && (kpos < SEQ) &&
                        (kpos >= qpos - WIN) && (kpos <= qpos + WIN);
                if (!vm[j]) s[i][j] = -1e30f;
                rowm = fmaxf(rowm, s[i][j]);
            }
            #pragma unroll
            for (int w = 1; w < 16; w <<= 1)
                rowm = fmaxf(rowm, __shfl_xor_sync(0xffffffffu, rowm, w));
            const float m_new = fmaxf(m_run[i], rowm);   // always finite (>= -1e30)
            const float alpha = __expf(m_run[i] - m_new); // -inf initial -> 0
            float rsum = 0.f;
            #pragma unroll
            for (int j = 0; j < 4; j++) {
                const float p = vm[j] ? __expf(s[i][j] - m_new) : 0.f;
                s[i][j] = p;
                rsum += p;
            }
            #pragma unroll
            for (int w = 1; w < 16; w <<= 1)
                rsum += __shfl_xor_sync(0xffffffffu, rsum, w);
            l_run[i] = l_run[i] * alpha + rsum;
            m_run[i] = m_new;
            #pragma unroll
            for (int j = 0; j < 4; j++) oacc[i][j] *= alpha;
            #pragma unroll
            for (int j = 0; j < 4; j++) Ps[(r0 + i) * 65 + c0 + j] = s[i][j];
        }
        __syncthreads();

        // O += P . V  (thread owns rows r0..r0+3, dims c0..c0+3)
        #pragma unroll 8
        for (int jj = 0; jj < 64; jj++) {
            float pr[4], vr[4];
            #pragma unroll
            for (int i = 0; i < 4; i++) pr[i] = Ps[(r0 + i) * 65 + jj];
            #pragma unroll
            for (int j = 0; j < 4; j++) vr[j] = Vs[jj * 65 + c0 + j];
            #pragma unroll
            for (int i = 0; i < 4; i++)
                #pragma unroll
                for (int j = 0; j < 4; j++)
                    oacc[i][j] = fmaf(pr[i], vr[j], oacc[i][j]);
        }
    }

    #pragma unroll
    for (int i = 0; i < 4; i++) {
        const float inv = 1.f / l_run[i];
        float* op = out + (size_t)(q0 + r0 + i) * HIDDIM + h * HD + c0;
        #pragma unroll
        for (int j = 0; j < 4; j++) op[j] = oacc[i][j] * inv;
    }
}

// ---------------------------------------------------------------------------
extern "C" void kernel_launch(void* const* d_in, const int* in_sizes, int n_in,
                              void* d_out, int out_size)
{
    const float* X  = (const float*)d_in[0];
    const float* Wq = (const float*)d_in[1];
    const float* bq = (const float*)d_in[2];
    const float* Wk = (const float*)d_in[3];
    const float* bk = (const float*)d_in[4];
    const float* Wv = (const float*)d_in[5];
    const float* bv = (const float*)d_in[6];
    float* out = (float*)d_out;

    void *qp, *kp, *vp;
    cudaGetSymbolAddress(&qp, g_Q);
    cudaGetSymbolAddress(&kp, g_K);
    cudaGetSymbolAddress(&vp, g_V);

    dim3 gg(HIDDIM / 128, SEQ / 128);   // (6, 64)
    qkv_gemm<<<gg, 256>>>(X, Wq, bq, (float*)qp, 0.125f);  // 1/sqrt(64)
    qkv_gemm<<<gg, 256>>>(X, Wk, bk, (float*)kp, 1.0f);
    qkv_gemm<<<gg, 256>>>(X, Wv, bv, (float*)vp, 1.0f);

    const size_t smem = 4 * 64 * 65 * sizeof(float);  // ~66.6 KB
    cudaFuncSetAttribute(swa_attn, cudaFuncAttributeMaxDynamicSharedMemorySize,
                         (int)smem);
    swa_attn<<<dim3(SEQ / 64, NHEAD), 256, smem>>>(out);
}

// round 3
// speedup vs baseline: 1.6884x; 1.6884x over previous
#include <cuda_runtime.h>
#include <cuda_bf16.h>
#include <math.h>
#include <stdint.h>

#define SEQ    8192
#define HIDDIM 768
#define NHEAD  12
#define HD     64
#define WIN    256

// ---------------- scratch (__device__ globals; allocation-free rule) -------
__device__ float g_Q[SEQ * HIDDIM];
__device__ float g_K[SEQ * HIDDIM];
__device__ float g_V[SEQ * HIDDIM];
__device__ __nv_bfloat16 g_Xhi[SEQ * HIDDIM];
__device__ __nv_bfloat16 g_Xlo[SEQ * HIDDIM];
__device__ __nv_bfloat16 g_Wthi[3][HIDDIM * HIDDIM];   // W^T, [N][K] K-major
__device__ __nv_bfloat16 g_Wtlo[3][HIDDIM * HIDDIM];

// ---------------- helpers ---------------------------------------------------
__device__ __forceinline__ uint32_t smem_u32(const void* p) {
    uint32_t a;
    asm("{ .reg .u64 t; cvta.to.shared.u64 t, %1; cvt.u32.u64 %0, t; }"
        : "=r"(a) : "l"(p));
    return a;
}
__device__ __forceinline__ void cp16(uint32_t dst, const void* src) {
    asm volatile("cp.async.cg.shared.global [%0], [%1], 16;"
                 :: "r"(dst), "l"(src) : "memory");
}
#define CP_COMMIT()  asm volatile("cp.async.commit_group;" ::: "memory")
#define CP_WAIT1()   asm volatile("cp.async.wait_group 1;" ::: "memory")
#define CP_WAIT0()   asm volatile("cp.async.wait_group 0;" ::: "memory")

__device__ __forceinline__ uint32_t sw128(uint32_t o) {
    return o ^ ((o >> 3) & 0x70);
}

#define LDSM_X4(r0, r1, r2, r3, addr) \
    asm volatile("ldmatrix.sync.aligned.m8n8.x4.shared.b16 {%0,%1,%2,%3}, [%4];" \
        : "=r"(r0), "=r"(r1), "=r"(r2), "=r"(r3) : "r"(addr))

#define MMA16816(c, a, b0, b1) \
    asm volatile("mma.sync.aligned.m16n8k16.row.col.f32.bf16.bf16.f32 " \
        "{%0,%1,%2,%3}, {%4,%5,%6,%7}, {%8,%9}, {%0,%1,%2,%3};" \
        : "+f"((c)[0]), "+f"((c)[1]), "+f"((c)[2]), "+f"((c)[3]) \
        : "r"((a)[0]), "r"((a)[1]), "r"((a)[2]), "r"((a)[3]), \
          "r"(b0), "r"(b1))

// ---------------- prep kernels ---------------------------------------------
__global__ void convert_x(const float* __restrict__ X,
                          __nv_bfloat16* __restrict__ hi,
                          __nv_bfloat16* __restrict__ lo, int n) {
    int i = blockIdx.x * blockDim.x + threadIdx.x;
    if (i < n) {
        float x = X[i];
        __nv_bfloat16 h = __float2bfloat16(x);
        hi[i] = h;
        lo[i] = __float2bfloat16(x - __bfloat162float(h));
    }
}

// W [K][N] row-major -> W^T hi/lo [N][K] row-major
__global__ void wt_convert(const float* __restrict__ W,
                           __nv_bfloat16* __restrict__ Thi,
                           __nv_bfloat16* __restrict__ Tlo) {
    __shared__ float tile[32][33];
    int tx = threadIdx.x, ty = threadIdx.y;   // 32 x 8
    int n0 = blockIdx.x * 32, k0 = blockIdx.y * 32;
    #pragma unroll
    for (int i = 0; i < 4; i++)
        tile[ty + i * 8][tx] = W[(size_t)(k0 + ty + i * 8) * HIDDIM + n0 + tx];
    __syncthreads();
    #pragma unroll
    for (int i = 0; i < 4; i++) {
        float v = tile[tx][ty + i * 8];               // W[k0+tx][n0+ty+i*8]
        __nv_bfloat16 h = __float2bfloat16(v);
        size_t o = (size_t)(n0 + ty + i * 8) * HIDDIM + k0 + tx;
        Thi[o] = h;
        Tlo[o] = __float2bfloat16(v - __bfloat162float(h));
    }
}

// ---------------- bf16-split HMMA GEMM --------------------------------------
// out[M,N] = (A @ Wt^T + bias) * scale;  A=[M,K] hi/lo, Wt=[N,K] hi/lo
// CTA 128x128, KC=64 (128B SW128 rows), double buffered cp.async.
// 8 warps: warp grid 4(M) x 2(N), warp tile 32x64.
#define KC      64
#define NCHUNK  (HIDDIM / KC)          // 12
#define TBYTES  (128 * 128)            // one operand tile: 128 rows x 128B
#define BUFB    (4 * TBYTES)           // Ah,Al,Bh,Bl
#define GEMM_SMEM (2 * BUFB)           // 131072 B

__global__ __launch_bounds__(256, 1) void gemm_mma(
    const __nv_bfloat16* __restrict__ Ah, const __nv_bfloat16* __restrict__ Al,
    const __nv_bfloat16* __restrict__ Bh, const __nv_bfloat16* __restrict__ Bl,
    const float* __restrict__ bias, float* __restrict__ out, float scale)
{
    extern __shared__ __align__(1024) char smem[];
    const uint32_t sb = smem_u32(smem);
    const int t = threadIdx.x;
    const int wid = t >> 5, lane = t & 31;
    const int wm = wid >> 1;           // 0..3 -> m offset wm*32
    const int wn = wid & 1;            // 0..1 -> n offset wn*64
    const int m0 = blockIdx.y * 128, n0 = blockIdx.x * 128;

    // ---- async load of one K-chunk into buffer b ----
    auto load_chunk = [&](int c, int b) {
        const int kk0 = c * KC;
        const uint32_t base = sb + b * BUFB;
        #pragma unroll
        for (int i = 0; i < 4; i++) {
            int cid = t + i * 256;            // 0..1023
            int row = cid >> 3, seg = cid & 7;
            uint32_t sw = sw128(row * 128 + seg * 16);
            size_t aoff = (size_t)(m0 + row) * HIDDIM + kk0 + seg * 8;
            size_t boff = (size_t)(n0 + row) * HIDDIM + kk0 + seg * 8;
            cp16(base + sw,              Ah + aoff);
            cp16(base + TBYTES + sw,     Al + aoff);
            cp16(base + 2 * TBYTES + sw, Bh + boff);
            cp16(base + 3 * TBYTES + sw, Bl + boff);
        }
        CP_COMMIT();
    };

    float acc[2][8][4];
    #pragma unroll
    for (int mi = 0; mi < 2; mi++)
        #pragma unroll
        for (int f = 0; f < 8; f++)
            #pragma unroll
            for (int r = 0; r < 4; r++) acc[mi][f][r] = 0.f;

    // ldmatrix per-lane address components (row within tile, byte col within row)
    const int lrow = (lane & 7) + ((lane >> 3) & 1) * 8;   // 0..15
    const int lcol = (lane >> 4) * 16;                     // 0 or 16

    load_chunk(0, 0);
    load_chunk(1, 1);

    for (int c = 0; c < NCHUNK; c++) {
        if (c < NCHUNK - 1) CP_WAIT1(); else CP_WAIT0();
        __syncthreads();

        const uint32_t base = sb + (c & 1) * BUFB;
        const uint32_t baseAh = base;
        const uint32_t baseAl = base + TBYTES;
        const uint32_t baseBh = base + 2 * TBYTES;
        const uint32_t baseBl = base + 3 * TBYTES;

        #pragma unroll
        for (int ks = 0; ks < 4; ks++) {           // 4 x k16 per chunk
            uint32_t ah[2][4], al[2][4];
            #pragma unroll
            for (int mi = 0; mi < 2; mi++) {
                uint32_t off = sw128((wm * 32 + mi * 16 + lrow) * 128 +
                                     ks * 32 + lcol);
                LDSM_X4(ah[mi][0], ah[mi][1], ah[mi][2], ah[mi][3], baseAh + off);
                LDSM_X4(al[mi][0], al[mi][1], al[mi][2], al[mi][3], baseAl + off);
            }
            #pragma unroll
            for (int g = 0; g < 4; g++) {          // 4 x n16 groups
                uint32_t boff = sw128((wn * 64 + g * 16 + lrow) * 128 +
                                      ks * 32 + lcol);
                uint32_t bh[4], bl[4];
                LDSM_X4(bh[0], bh[1], bh[2], bh[3], baseBh + boff);
                LDSM_X4(bl[0], bl[1], bl[2], bl[3], baseBl + boff);
                #pragma unroll
                for (int mi = 0; mi < 2; mi++) {
                    // n8 half 0: frags {r0, r2}; half 1: {r1, r3}
                    MMA16816(acc[mi][g * 2 + 0], ah[mi], bh[0], bh[2]);
                    MMA16816(acc[mi][g * 2 + 0], ah[mi], bl[0], bl[2]);
                    MMA16816(acc[mi][g * 2 + 0], al[mi], bh[0], bh[2]);
                    MMA16816(acc[mi][g * 2 + 1], ah[mi], bh[1], bh[3]);
                    MMA16816(acc[mi][g * 2 + 1], ah[mi], bl[1], bl[3]);
                    MMA16816(acc[mi][g * 2 + 1], al[mi], bh[1], bh[3]);
                }
            }
        }
        __syncthreads();
        if (c + 2 < NCHUNK) load_chunk(c + 2, c & 1);
    }

    // ---- epilogue: registers -> gmem with bias + scale ----
    #pragma unroll
    for (int mi = 0; mi < 2; mi++) {
        const int mrow = m0 + wm * 32 + mi * 16 + (lane >> 2);
        #pragma unroll
        for (int f = 0; f < 8; f++) {
            const int col = n0 + wn * 64 + (f >> 1) * 16 + (f & 1) * 8 +
                            (lane & 3) * 2;
            const float b0 = bias[col], b1 = bias[col + 1];
            float2 w0, w1;
            w0.x = (acc[mi][f][0] + b0) * scale;
            w0.y = (acc[mi][f][1] + b1) * scale;
            w1.x = (acc[mi][f][2] + b0) * scale;
            w1.y = (acc[mi][f][3] + b1) * scale;
            *(float2*)(out + (size_t)mrow * HIDDIM + col) = w0;
            *(float2*)(out + (size_t)(mrow + 8) * HIDDIM + col) = w1;
        }
    }
}

// ---------------------------------------------------------------------------
// Sliding-window flash attention (unchanged from passing R1 kernel).
// ---------------------------------------------------------------------------
__global__ __launch_bounds__(256) void swa_attn(float* __restrict__ out)
{
    extern __shared__ float sm[];
    float* Qs = sm;
    float* Ks = sm + 64 * 65;
    float* Vs = sm + 2 * 64 * 65;
    float* Ps = sm + 3 * 64 * 65;

    const int q0 = blockIdx.x * 64;
    const int h  = blockIdx.y;
    const int t  = threadIdx.x;
    const int ty = t >> 4;
    const int tx = t & 15;
    const int r0 = ty << 2;
    const int c0 = tx << 2;

    {
        const int row = t >> 2;
        const int seg = (t & 3) << 4;
        const float* src = g_Q + (size_t)(q0 + row) * HIDDIM + h * HD + seg;
        #pragma unroll
        for (int i = 0; i < 4; i++) {
            float4 v = *(const float4*)(src + i * 4);
            float* d = Qs + row * 65 + seg + i * 4;
            d[0] = v.x; d[1] = v.y; d[2] = v.z; d[3] = v.w;
        }
    }

    float m_run[4], l_run[4], oacc[4][4];
    #pragma unroll
    for (int i = 0; i < 4; i++) {
        m_run[i] = -INFINITY; l_run[i] = 0.f;
        #pragma unroll
        for (int j = 0; j < 4; j++) oacc[i][j] = 0.f;
    }

    for (int kt = 0; kt < 9; kt++) {
        const int kbase = q0 - WIN + kt * 64;

        __syncthreads();
        {
            const int row  = t >> 2;
            const int seg  = (t & 3) << 4;
            const int krow = kbase + row;
            const bool ok  = (krow >= 0) && (krow < SEQ);
            const size_t off = (size_t)(ok ? krow : 0) * HIDDIM + h * HD + seg;
            const float* ksrc = g_K + off;
            const float* vsrc = g_V + off;
            #pragma unroll
            for (int i = 0; i < 4; i++) {
                float4 kv = ok ? *(const float4*)(ksrc + i * 4) : make_float4(0, 0, 0, 0);
                float4 vv = ok ? *(const float4*)(vsrc + i * 4) : make_float4(0, 0, 0, 0);
                float* kd = Ks + row * 65 + seg + i * 4;
                kd[0] = kv.x; kd[1] = kv.y; kd[2] = kv.z; kd[3] = kv.w;
                float* vd = Vs + row * 65 + seg + i * 4;
                vd[0] = vv.x; vd[1] = vv.y; vd[2] = vv.z; vd[3] = vv.w;
            }
        }
        __syncthreads();

        float s[4][4];
        #pragma unroll
        for (int i = 0; i < 4; i++)
            #pragma unroll
            for (int j = 0; j < 4; j++) s[i][j] = 0.f;

        #pragma unroll 8
        for (int kk = 0; kk < 64; kk++) {
            float a[4], b[4];
            #pragma unroll
            for (int i = 0; i < 4; i++) a[i] = Qs[(r0 + i) * 65 + kk];
            #pragma unroll
            for (int j = 0; j < 4; j++) b[j] = Ks[(c0 + j) * 65 + kk];
            #pragma unroll
            for (int i = 0; i < 4; i++)
                #pragma unroll
                for (int j = 0; j < 4; j++)
                    s[i][j] = fmaf(a[i], b[j], s[i][j]);
        }

        #pragma unroll
        for (int i = 0; i < 4; i++) {
            const int qpos = q0 + r0 + i;
            bool vm[4];
            float rowm = -1e30f;
            #pragma unroll
            for (int j = 0; j < 4; j++) {
                const int kpos = kbase + c0 + j;
                vm[j] = (kpos >= 0) && (kpos < SEQ) &&
                        (kpos >= qpos - WIN) && (kpos <= qpos + WIN);
                if (!vm[j]) s[i][j] = -1e30f;
                rowm = fmaxf(rowm, s[i][j]);
            }
            #pragma unroll
            for (int w = 1; w < 16; w <<= 1)
                rowm = fmaxf(rowm, __shfl_xor_sync(0xffffffffu, rowm, w));
            const float m_new = fmaxf(m_run[i], rowm);
            const float alpha = __expf(m_run[i] - m_new);
            float rsum = 0.f;
            #pragma unroll
            for (int j = 0; j < 4; j++) {
                const float p = vm[j] ? __expf(s[i][j] - m_new) : 0.f;
                s[i][j] = p;
                rsum += p;
            }
            #pragma unroll
            for (int w = 1; w < 16; w <<= 1)
                rsum += __shfl_xor_sync(0xffffffffu, rsum, w);
            l_run[i] = l_run[i] * alpha + rsum;
            m_run[i] = m_new;
            #pragma unroll
            for (int j = 0; j < 4; j++) oacc[i][j] *= alpha;
            #pragma unroll
            for (int j = 0; j < 4; j++) Ps[(r0 + i) * 65 + c0 + j] = s[i][j];
        }
        __syncthreads();

        #pragma unroll 8
        for (int jj = 0; jj < 64; jj++) {
            float pr[4], vr[4];
            #pragma unroll
            for (int i = 0; i < 4; i++) pr[i] = Ps[(r0 + i) * 65 + jj];
            #pragma unroll
            for (int j = 0; j < 4; j++) vr[j] = Vs[jj * 65 + c0 + j];
            #pragma unroll
            for (int i = 0; i < 4; i++)
                #pragma unroll
                for (int j = 0; j < 4; j++)
                    oacc[i][j] = fmaf(pr[i], vr[j], oacc[i][j]);
        }
    }

    #pragma unroll
    for (int i = 0; i < 4; i++) {
        const float inv = 1.f / l_run[i];
        float* op = out + (size_t)(q0 + r0 + i) * HIDDIM + h * HD + c0;
        #pragma unroll
        for (int j = 0; j < 4; j++) op[j] = oacc[i][j] * inv;
    }
}

// ---------------------------------------------------------------------------
extern "C" void kernel_launch(void* const* d_in, const int* in_sizes, int n_in,
                              void* d_out, int out_size)
{
    const float* X  = (const float*)d_in[0];
    const float* Wq = (const float*)d_in[1];
    const float* bq = (const float*)d_in[2];
    const float* Wk = (const float*)d_in[3];
    const float* bk = (const float*)d_in[4];
    const float* Wv = (const float*)d_in[5];
    const float* bv = (const float*)d_in[6];
    float* out = (float*)d_out;

    void *qp, *kp, *vp, *xh, *xl, *wh, *wl;
    cudaGetSymbolAddress(&qp, g_Q);
    cudaGetSymbolAddress(&kp, g_K);
    cudaGetSymbolAddress(&vp, g_V);
    cudaGetSymbolAddress(&xh, g_Xhi);
    cudaGetSymbolAddress(&xl, g_Xlo);
    cudaGetSymbolAddress(&wh, g_Wthi);
    cudaGetSymbolAddress(&wl, g_Wtlo);

    __nv_bfloat16* Xhi = (__nv_bfloat16*)xh;
    __nv_bfloat16* Xlo = (__nv_bfloat16*)xl;
    __nv_bfloat16* Whi = (__nv_bfloat16*)wh;
    __nv_bfloat16* Wlo = (__nv_bfloat16*)wl;
    const size_t WSZ = (size_t)HIDDIM * HIDDIM;

    // prep: X split + W transpose/split
    const int nX = SEQ * HIDDIM;
    convert_x<<<(nX + 255) / 256, 256>>>(X, Xhi, Xlo, nX);
    dim3 wtg(HIDDIM / 32, HIDDIM / 32), wtb(32, 8);
    wt_convert<<<wtg, wtb>>>(Wq, Whi + 0 * WSZ, Wlo + 0 * WSZ);
    wt_convert<<<wtg, wtb>>>(Wk, Whi + 1 * WSZ, Wlo + 1 * WSZ);
    wt_convert<<<wtg, wtb>>>(Wv, Whi + 2 * WSZ, Wlo + 2 * WSZ);

    // HMMA QKV GEMMs
    cudaFuncSetAttribute(gemm_mma, cudaFuncAttributeMaxDynamicSharedMemorySize,
                         GEMM_SMEM);
    dim3 gg(HIDDIM / 128, SEQ / 128);   // (6, 64)
    gemm_mma<<<gg, 256, GEMM_SMEM>>>(Xhi, Xlo, Whi + 0 * WSZ, Wlo + 0 * WSZ,
                                     bq, (float*)qp, 0.125f);  // 1/sqrt(64)
    gemm_mma<<<gg, 256, GEMM_SMEM>>>(Xhi, Xlo, Whi + 1 * WSZ, Wlo + 1 * WSZ,
                                     bk, (float*)kp, 1.0f);
    gemm_mma<<<gg, 256, GEMM_SMEM>>>(Xhi, Xlo, Whi + 2 * WSZ, Wlo + 2 * WSZ,
                                     bv, (float*)vp, 1.0f);

    // attention
    const size_t smem = 4 * 64 * 65 * sizeof(float);
    cudaFuncSetAttribute(swa_attn, cudaFuncAttributeMaxDynamicSharedMemorySize,
                         (int)smem);
    swa_attn<<<dim3(SEQ / 64, NHEAD), 256, smem>>>(out);
}

// round 4
// speedup vs baseline: 1.9497x; 1.1548x over previous
#include <cuda_runtime.h>
#include <cuda_bf16.h>
#include <math.h>
#include <stdint.h>

#define SEQ    8192
#define HIDDIM 768
#define NHEAD  12
#define HD     64
#define WIN    256

// ---------------- scratch (__device__ globals; allocation-free rule) -------
__device__ __nv_bfloat16 g_Qh[SEQ * HIDDIM];
__device__ __nv_bfloat16 g_Ql[SEQ * HIDDIM];
__device__ __nv_bfloat16 g_Kh[SEQ * HIDDIM];
__device__ __nv_bfloat16 g_Kl[SEQ * HIDDIM];
__device__ __nv_bfloat16 g_Vh[SEQ * HIDDIM];
__device__ __nv_bfloat16 g_Vl[SEQ * HIDDIM];
__device__ __nv_bfloat16 g_Xhi[SEQ * HIDDIM];
__device__ __nv_bfloat16 g_Xlo[SEQ * HIDDIM];
__device__ __nv_bfloat16 g_Wthi[3][HIDDIM * HIDDIM];   // W^T, [N][K] K-major
__device__ __nv_bfloat16 g_Wtlo[3][HIDDIM * HIDDIM];

// ---------------- helpers ---------------------------------------------------
__device__ __forceinline__ uint32_t smem_u32(const void* p) {
    uint32_t a;
    asm("{ .reg .u64 t; cvta.to.shared.u64 t, %1; cvt.u32.u64 %0, t; }"
        : "=r"(a) : "l"(p));
    return a;
}
__device__ __forceinline__ void cp16(uint32_t dst, const void* src) {
    asm volatile("cp.async.cg.shared.global [%0], [%1], 16;"
                 :: "r"(dst), "l"(src) : "memory");
}
#define CP_COMMIT()  asm volatile("cp.async.commit_group;" ::: "memory")
#define CP_WAIT1()   asm volatile("cp.async.wait_group 1;" ::: "memory")
#define CP_WAIT0()   asm volatile("cp.async.wait_group 0;" ::: "memory")

__device__ __forceinline__ uint32_t sw128(uint32_t o) {
    return o ^ ((o >> 3) & 0x70);
}

#define LDSM_X4(r0, r1, r2, r3, addr) \
    asm volatile("ldmatrix.sync.aligned.m8n8.x4.shared.b16 {%0,%1,%2,%3}, [%4];" \
        : "=r"(r0), "=r"(r1), "=r"(r2), "=r"(r3) : "r"(addr))

#define LDSM_X4_T(r0, r1, r2, r3, addr) \
    asm volatile("ldmatrix.sync.aligned.m8n8.x4.trans.shared.b16 {%0,%1,%2,%3}, [%4];" \
        : "=r"(r0), "=r"(r1), "=r"(r2), "=r"(r3) : "r"(addr))

#define MMA16816(c, a, b0, b1) \
    asm volatile("mma.sync.aligned.m16n8k16.row.col.f32.bf16.bf16.f32 " \
        "{%0,%1,%2,%3}, {%4,%5,%6,%7}, {%8,%9}, {%0,%1,%2,%3};" \
        : "+f"((c)[0]), "+f"((c)[1]), "+f"((c)[2]), "+f"((c)[3]) \
        : "r"((a)[0]), "r"((a)[1]), "r"((a)[2]), "r"((a)[3]), \
          "r"(b0), "r"(b1))

__device__ __forceinline__ void pack_hl(float p0, float p1,
                                        uint32_t& hw, uint32_t& lw) {
    __nv_bfloat16 h0 = __float2bfloat16(p0), h1 = __float2bfloat16(p1);
    hw = (uint32_t)__bfloat16_as_ushort(h0) |
         ((uint32_t)__bfloat16_as_ushort(h1) << 16);
    __nv_bfloat16 l0 = __float2bfloat16(p0 - __bfloat162float(h0));
    __nv_bfloat16 l1 = __float2bfloat16(p1 - __bfloat162float(h1));
    lw = (uint32_t)__bfloat16_as_ushort(l0) |
         ((uint32_t)__bfloat16_as_ushort(l1) << 16);
}

// ---------------- prep kernels ---------------------------------------------
__global__ void convert_x(const float* __restrict__ X,
                          __nv_bfloat16* __restrict__ hi,
                          __nv_bfloat16* __restrict__ lo, int n) {
    int i = blockIdx.x * blockDim.x + threadIdx.x;
    if (i < n) {
        float x = X[i];
        __nv_bfloat16 h = __float2bfloat16(x);
        hi[i] = h;
        lo[i] = __float2bfloat16(x - __bfloat162float(h));
    }
}

// W [K][N] row-major -> W^T hi/lo [N][K] row-major
__global__ void wt_convert(const float* __restrict__ W,
                           __nv_bfloat16* __restrict__ Thi,
                           __nv_bfloat16* __restrict__ Tlo) {
    __shared__ float tile[32][33];
    int tx = threadIdx.x, ty = threadIdx.y;   // 32 x 8
    int n0 = blockIdx.x * 32, k0 = blockIdx.y * 32;
    #pragma unroll
    for (int i = 0; i < 4; i++)
        tile[ty + i * 8][tx] = W[(size_t)(k0 + ty + i * 8) * HIDDIM + n0 + tx];
    __syncthreads();
    #pragma unroll
    for (int i = 0; i < 4; i++) {
        float v = tile[tx][ty + i * 8];
        __nv_bfloat16 h = __float2bfloat16(v);
        size_t o = (size_t)(n0 + ty + i * 8) * HIDDIM + k0 + tx;
        Thi[o] = h;
        Tlo[o] = __float2bfloat16(v - __bfloat162float(h));
    }
}

// ---------------- bf16-split HMMA GEMM (epilogue -> bf16 hi/lo) -------------
#define KC      64
#define NCHUNK  (HIDDIM / KC)          // 12
#define TBYTES  (128 * 128)
#define BUFB    (4 * TBYTES)
#define GEMM_SMEM (2 * BUFB)           // 131072 B

__global__ __launch_bounds__(256, 1) void gemm_mma(
    const __nv_bfloat16* __restrict__ Ah, const __nv_bfloat16* __restrict__ Al,
    const __nv_bfloat16* __restrict__ Bh, const __nv_bfloat16* __restrict__ Bl,
    const float* __restrict__ bias,
    __nv_bfloat16* __restrict__ Ohi, __nv_bfloat16* __restrict__ Olo,
    float scale)
{
    extern __shared__ __align__(1024) char smem[];
    const uint32_t sb = smem_u32(smem);
    const int t = threadIdx.x;
    const int wid = t >> 5, lane = t & 31;
    const int wm = wid >> 1;
    const int wn = wid & 1;
    const int m0 = blockIdx.y * 128, n0 = blockIdx.x * 128;

    auto load_chunk = [&](int c, int b) {
        const int kk0 = c * KC;
        const uint32_t base = sb + b * BUFB;
        #pragma unroll
        for (int i = 0; i < 4; i++) {
            int cid = t + i * 256;
            int row = cid >> 3, seg = cid & 7;
            uint32_t sw = sw128(row * 128 + seg * 16);
            size_t aoff = (size_t)(m0 + row) * HIDDIM + kk0 + seg * 8;
            size_t boff = (size_t)(n0 + row) * HIDDIM + kk0 + seg * 8;
            cp16(base + sw,              Ah + aoff);
            cp16(base + TBYTES + sw,     Al + aoff);
            cp16(base + 2 * TBYTES + sw, Bh + boff);
            cp16(base + 3 * TBYTES + sw, Bl + boff);
        }
        CP_COMMIT();
    };

    float acc[2][8][4];
    #pragma unroll
    for (int mi = 0; mi < 2; mi++)
        #pragma unroll
        for (int f = 0; f < 8; f++)
            #pragma unroll
            for (int r = 0; r < 4; r++) acc[mi][f][r] = 0.f;

    const int lrow = (lane & 7) + ((lane >> 3) & 1) * 8;
    const int lcol = (lane >> 4) * 16;

    load_chunk(0, 0);
    load_chunk(1, 1);

    for (int c = 0; c < NCHUNK; c++) {
        if (c < NCHUNK - 1) CP_WAIT1(); else CP_WAIT0();
        __syncthreads();

        const uint32_t base = sb + (c & 1) * BUFB;
        const uint32_t baseAh = base;
        const uint32_t baseAl = base + TBYTES;
        const uint32_t baseBh = base + 2 * TBYTES;
        const uint32_t baseBl = base + 3 * TBYTES;

        #pragma unroll
        for (int ks = 0; ks < 4; ks++) {
            uint32_t ah[2][4], al[2][4];
            #pragma unroll
            for (int mi = 0; mi < 2; mi++) {
                uint32_t off = sw128((wm * 32 + mi * 16 + lrow) * 128 +
                                     ks * 32 + lcol);
                LDSM_X4(ah[mi][0], ah[mi][1], ah[mi][2], ah[mi][3], baseAh + off);
                LDSM_X4(al[mi][0], al[mi][1], al[mi][2], al[mi][3], baseAl + off);
            }
            #pragma unroll
            for (int g = 0; g < 4; g++) {
                uint32_t boff = sw128((wn * 64 + g * 16 + lrow) * 128 +
                                      ks * 32 + lcol);
                uint32_t bh[4], bl[4];
                LDSM_X4(bh[0], bh[1], bh[2], bh[3], baseBh + boff);
                LDSM_X4(bl[0], bl[1], bl[2], bl[3], baseBl + boff);
                #pragma unroll
                for (int mi = 0; mi < 2; mi++) {
                    MMA16816(acc[mi][g * 2 + 0], ah[mi], bh[0], bh[2]);
                    MMA16816(acc[mi][g * 2 + 0], ah[mi], bl[0], bl[2]);
                    MMA16816(acc[mi][g * 2 + 0], al[mi], bh[0], bh[2]);
                    MMA16816(acc[mi][g * 2 + 1], ah[mi], bh[1], bh[3]);
                    MMA16816(acc[mi][g * 2 + 1], ah[mi], bl[1], bl[3]);
                    MMA16816(acc[mi][g * 2 + 1], al[mi], bh[1], bh[3]);
                }
            }
        }
        __syncthreads();
        if (c + 2 < NCHUNK) load_chunk(c + 2, c & 1);
    }

    // epilogue: +bias, *scale, split into bf16 hi/lo
    #pragma unroll
    for (int mi = 0; mi < 2; mi++) {
        const int mrow = m0 + wm * 32 + mi * 16 + (lane >> 2);
        #pragma unroll
        for (int f = 0; f < 8; f++) {
            const int col = n0 + wn * 64 + (f >> 1) * 16 + (f & 1) * 8 +
                            (lane & 3) * 2;
            const float b0 = bias[col], b1 = bias[col + 1];
            float v0 = (acc[mi][f][0] + b0) * scale;
            float v1 = (acc[mi][f][1] + b1) * scale;
            float v2 = (acc[mi][f][2] + b0) * scale;
            float v3 = (acc[mi][f][3] + b1) * scale;
            uint32_t hw0, lw0, hw1, lw1;
            pack_hl(v0, v1, hw0, lw0);
            pack_hl(v2, v3, hw1, lw1);
            *(uint32_t*)(Ohi + (size_t)mrow * HIDDIM + col) = hw0;
            *(uint32_t*)(Olo + (size_t)mrow * HIDDIM + col) = lw0;
            *(uint32_t*)(Ohi + (size_t)(mrow + 8) * HIDDIM + col) = hw1;
            *(uint32_t*)(Olo + (size_t)(mrow + 8) * HIDDIM + col) = lw1;
        }
    }
}

// ---------------------------------------------------------------------------
// Tensor-core sliding-window flash attention.
// Block = 64 queries x 1 head, 4 warps (warp w owns queries w*16..w*16+15).
// K tiles of 64 keys, 9 per block, double-buffered cp.async.
// Scores in base-2 logits (log2e folded into Q GEMM scale).
// ---------------------------------------------------------------------------
#define AT_QOFF   0
#define AT_BUF    16384
#define AT_BUFSZ  32768
#define AT_SMEM   (16384 + 2 * 32768)   // 81920

__global__ __launch_bounds__(128) void swa_mma(
    const __nv_bfloat16* __restrict__ Qh_, const __nv_bfloat16* __restrict__ Ql_,
    const __nv_bfloat16* __restrict__ Kh_, const __nv_bfloat16* __restrict__ Kl_,
    const __nv_bfloat16* __restrict__ Vh_, const __nv_bfloat16* __restrict__ Vl_,
    float* __restrict__ out)
{
    extern __shared__ __align__(1024) char smem[];
    const uint32_t sb = smem_u32(smem);
    const int t = threadIdx.x, lane = t & 31, w = t >> 5;
    const int q0 = blockIdx.x * 64;
    const int h  = blockIdx.y;
    const int cb = h * HD;                // gmem col base for this head

    const uint32_t bQh = sb + AT_QOFF, bQl = bQh + 8192;

    auto ld_q = [&]() {
        #pragma unroll
        for (int i = 0; i < 4; i++) {
            int cid = t + i * 128;
            int row = cid >> 3, seg = cid & 7;
            uint32_t sw = sw128(row * 128 + seg * 16);
            size_t g = (size_t)(q0 + row) * HIDDIM + cb + seg * 8;
            cp16(bQh + sw, Qh_ + g);
            cp16(bQl + sw, Ql_ + g);
        }
    };
    auto ld_kv = [&](int kt, int buf) {
        const int kbase = q0 - WIN + kt * 64;
        const uint32_t bb = sb + AT_BUF + buf * AT_BUFSZ;
        #pragma unroll
        for (int i = 0; i < 4; i++) {
            int cid = t + i * 128;
            int row = cid >> 3, seg = cid & 7;
            int kr = kbase + row;
            int cr = ((unsigned)kr < SEQ) ? kr : 0;
            uint32_t sw = sw128(row * 128 + seg * 16);
            size_t g = (size_t)cr * HIDDIM + cb + seg * 8;
            cp16(bb + sw,          Kh_ + g);
            cp16(bb + 8192 + sw,   Kl_ + g);
            cp16(bb + 16384 + sw,  Vh_ + g);
            cp16(bb + 24576 + sw,  Vl_ + g);
        }
    };

    ld_q(); ld_kv(0, 0); CP_COMMIT();
    ld_kv(1, 1); CP_COMMIT();

    const int lrow = (lane & 7) + ((lane >> 3) & 1) * 8;
    const int lcol = (lane >> 4) * 16;

    float oacc[8][4];
    #pragma unroll
    for (int n = 0; n < 8; n++)
        #pragma unroll
        for (int r = 0; r < 4; r++) oacc[n][r] = 0.f;
    float m0r = -1e30f, m1r = -1e30f, l0 = 0.f, l1 = 0.f;

    CP_WAIT1();
    __syncthreads();

    // Q fragments (resident across all tiles)
    uint32_t qh[4][4], ql[4][4];
    #pragma unroll
    for (int ks = 0; ks < 4; ks++) {
        uint32_t off = sw128((w * 16 + lrow) * 128 + ks * 32 + lcol);
        LDSM_X4(qh[ks][0], qh[ks][1], qh[ks][2], qh[ks][3], bQh + off);
        LDSM_X4(ql[ks][0], ql[ks][1], ql[ks][2], ql[ks][3], bQl + off);
    }

    const int r0q = q0 + w * 16 + (lane >> 2);   // first of this thread's rows

    for (int kt = 0; kt < 9; kt++) {
        if (kt) {
            if (kt < 8) CP_WAIT1(); else CP_WAIT0();
            __syncthreads();
        }
        const uint32_t bb = sb + AT_BUF + (kt & 1) * AT_BUFSZ;
        const uint32_t bKh = bb, bKl = bb + 8192;
        const uint32_t bVh = bb + 16384, bVl = bb + 24576;
        const int kbase = q0 - WIN + kt * 64;

        // ---- S = Q K^T ----
        float sc[8][4];
        #pragma unroll
        for (int n = 0; n < 8; n++)
            #pragma unroll
            for (int r = 0; r < 4; r++) sc[n][r] = 0.f;

        #pragma unroll
        for (int g = 0; g < 4; g++) {
            #pragma unroll
            for (int ks = 0; ks < 4; ks++) {
                uint32_t off = sw128((g * 16 + lrow) * 128 + ks * 32 + lcol);
                uint32_t h0, h1, h2, h3, e0, e1, e2, e3;
                LDSM_X4(h0, h1, h2, h3, bKh + off);
                LDSM_X4(e0, e1, e2, e3, bKl + off);
                MMA16816(sc[g * 2 + 0], qh[ks], h0, h2);
                MMA16816(sc[g * 2 + 0], qh[ks], e0, e2);
                MMA16816(sc[g * 2 + 0], ql[ks], h0, h2);
                MMA16816(sc[g * 2 + 1], qh[ks], h1, h3);
                MMA16816(sc[g * 2 + 1], qh[ks], e1, e3);
                MMA16816(sc[g * 2 + 1], ql[ks], h1, h3);
            }
        }

        // ---- mask + online softmax (base-2) ----
        float mx0 = -1e30f, mx1 = -1e30f;
        #pragma unroll
        for (int n = 0; n < 8; n++) {
            const int k0p = kbase + n * 8 + (lane & 3) * 2;
            const int k1p = k0p + 1;
            bool v00 = ((unsigned)k0p < SEQ) && (unsigned)(k0p - r0q + WIN) <= 2 * WIN;
            bool v01 = ((unsigned)k1p < SEQ) && (unsigned)(k1p - r0q + WIN) <= 2 * WIN;
            bool v10 = ((unsigned)k0p < SEQ) && (unsigned)(k0p - (r0q + 8) + WIN) <= 2 * WIN;
            bool v11 = ((unsigned)k1p < SEQ) && (unsigned)(k1p - (r0q + 8) + WIN) <= 2 * WIN;
            if (!v00) sc[n][0] = -1e30f;
            if (!v01) sc[n][1] = -1e30f;
            if (!v10) sc[n][2] = -1e30f;
            if (!v11) sc[n][3] = -1e30f;
            mx0 = fmaxf(mx0, fmaxf(sc[n][0], sc[n][1]));
            mx1 = fmaxf(mx1, fmaxf(sc[n][2], sc[n][3]));
        }
        mx0 = fmaxf(mx0, __shfl_xor_sync(0xffffffffu, mx0, 1));
        mx0 = fmaxf(mx0, __shfl_xor_sync(0xffffffffu, mx0, 2));
        mx1 = fmaxf(mx1, __shfl_xor_sync(0xffffffffu, mx1, 1));
        mx1 = fmaxf(mx1, __shfl_xor_sync(0xffffffffu, mx1, 2));

        const float mn0 = fmaxf(m0r, mx0), mn1 = fmaxf(m1r, mx1);
        const float a0 = exp2f(m0r - mn0), a1 = exp2f(m1r - mn1);
        m0r = mn0; m1r = mn1;

        float s0 = 0.f, s1 = 0.f;
        #pragma unroll
        for (int n = 0; n < 8; n++) {
            sc[n][0] = exp2f(sc[n][0] - mn0);
            sc[n][1] = exp2f(sc[n][1] - mn0);
            sc[n][2] = exp2f(sc[n][2] - mn1);
            sc[n][3] = exp2f(sc[n][3] - mn1);
            s0 += sc[n][0] + sc[n][1];
            s1 += sc[n][2] + sc[n][3];
        }
        s0 += __shfl_xor_sync(0xffffffffu, s0, 1);
        s0 += __shfl_xor_sync(0xffffffffu, s0, 2);
        s1 += __shfl_xor_sync(0xffffffffu, s1, 1);
        s1 += __shfl_xor_sync(0xffffffffu, s1, 2);
        l0 = l0 * a0 + s0;
        l1 = l1 * a1 + s1;
        #pragma unroll
        for (int n = 0; n < 8; n++) {
            oacc[n][0] *= a0; oacc[n][1] *= a0;
            oacc[n][2] *= a1; oacc[n][3] *= a1;
        }

        // ---- repack P into A-fragments (hi/lo) ----
        uint32_t ph[4][4], pl[4][4];
        #pragma unroll
        for (int g = 0; g < 4; g++) {
            pack_hl(sc[2 * g][0],     sc[2 * g][1],     ph[g][0], pl[g][0]);
            pack_hl(sc[2 * g][2],     sc[2 * g][3],     ph[g][1], pl[g][1]);
            pack_hl(sc[2 * g + 1][0], sc[2 * g + 1][1], ph[g][2], pl[g][2]);
            pack_hl(sc[2 * g + 1][2], sc[2 * g + 1][3], ph[g][3], pl[g][3]);
        }

        // ---- O += P V ----
        #pragma unroll
        for (int g = 0; g < 4; g++) {
            #pragma unroll
            for (int t2 = 0; t2 < 4; t2++) {
                uint32_t voff = sw128((g * 16 + (lane & 15)) * 128 +
                                      t2 * 32 + (lane >> 4) * 16);
                uint32_t v0, v1, v2, v3, u0, u1, u2, u3;
                LDSM_X4_T(v0, v1, v2, v3, bVh + voff);
                LDSM_X4_T(u0, u1, u2, u3, bVl + voff);
                MMA16816(oacc[2 * t2 + 0], ph[g], v0, v1);
                MMA16816(oacc[2 * t2 + 0], ph[g], u0, u1);
                MMA16816(oacc[2 * t2 + 0], pl[g], v0, v1);
                MMA16816(oacc[2 * t2 + 1], ph[g], v2, v3);
                MMA16816(oacc[2 * t2 + 1], ph[g], u2, u3);
                MMA16816(oacc[2 * t2 + 1], pl[g], v2, v3);
            }
        }

        __syncthreads();
        if (kt + 2 <= 8) { ld_kv(kt + 2, kt & 1); CP_COMMIT(); }
    }

    // ---- epilogue ----
    const float i0 = 1.f / l0, i1 = 1.f / l1;
    #pragma unroll
    for (int n = 0; n < 8; n++) {
        const int col = cb + n * 8 + (lane & 3) * 2;
        float2 w0, w1;
        w0.x = oacc[n][0] * i0; w0.y = oacc[n][1] * i0;
        w1.x = oacc[n][2] * i1; w1.y = oacc[n][3] * i1;
        *(float2*)(out + (size_t)r0q * HIDDIM + col) = w0;
        *(float2*)(out + (size_t)(r0q + 8) * HIDDIM + col) = w1;
    }
}

// ---------------------------------------------------------------------------
extern "C" void kernel_launch(void* const* d_in, const int* in_sizes, int n_in,
                              void* d_out, int out_size)
{
    const float* X  = (const float*)d_in[0];
    const float* Wq = (const float*)d_in[1];
    const float* bq = (const float*)d_in[2];
    const float* Wk = (const float*)d_in[3];
    const float* bk = (const float*)d_in[4];
    const float* Wv = (const float*)d_in[5];
    const float* bv = (const float*)d_in[6];
    float* out = (float*)d_out;

    void *qh, *ql, *kh, *kl, *vh, *vl, *xh, *xl, *wh, *wl;
    cudaGetSymbolAddress(&qh, g_Qh);  cudaGetSymbolAddress(&ql, g_Ql);
    cudaGetSymbolAddress(&kh, g_Kh);  cudaGetSymbolAddress(&kl, g_Kl);
    cudaGetSymbolAddress(&vh, g_Vh);  cudaGetSymbolAddress(&vl, g_Vl);
    cudaGetSymbolAddress(&xh, g_Xhi); cudaGetSymbolAddress(&xl, g_Xlo);
    cudaGetSymbolAddress(&wh, g_Wthi); cudaGetSymbolAddress(&wl, g_Wtlo);

    __nv_bfloat16* Xhi = (__nv_bfloat16*)xh;
    __nv_bfloat16* Xlo = (__nv_bfloat16*)xl;
    __nv_bfloat16* Whi = (__nv_bfloat16*)wh;
    __nv_bfloat16* Wlo = (__nv_bfloat16*)wl;
    const size_t WSZ = (size_t)HIDDIM * HIDDIM;

    const int nX = SEQ * HIDDIM;
    convert_x<<<(nX + 255) / 256, 256>>>(X, Xhi, Xlo, nX);
    dim3 wtg(HIDDIM / 32, HIDDIM / 32), wtb(32, 8);
    wt_convert<<<wtg, wtb>>>(Wq, Whi + 0 * WSZ, Wlo + 0 * WSZ);
    wt_convert<<<wtg, wtb>>>(Wk, Whi + 1 * WSZ, Wlo + 1 * WSZ);
    wt_convert<<<wtg, wtb>>>(Wv, Whi + 2 * WSZ, Wlo + 2 * WSZ);

    cudaFuncSetAttribute(gemm_mma, cudaFuncAttributeMaxDynamicSharedMemorySize,
                         GEMM_SMEM);
    dim3 gg(HIDDIM / 128, SEQ / 128);
    // Q scale = (1/sqrt(64)) * log2(e)  -> softmax in base-2 logits
    const float qscale = 0.125f * 1.4426950408889634f;
    gemm_mma<<<gg, 256, GEMM_SMEM>>>(Xhi, Xlo, Whi + 0 * WSZ, Wlo + 0 * WSZ,
                                     bq, (__nv_bfloat16*)qh, (__nv_bfloat16*)ql,
                                     qscale);
    gemm_mma<<<gg, 256, GEMM_SMEM>>>(Xhi, Xlo, Whi + 1 * WSZ, Wlo + 1 * WSZ,
                                     bk, (__nv_bfloat16*)kh, (__nv_bfloat16*)kl,
                                     1.0f);
    gemm_mma<<<gg, 256, GEMM_SMEM>>>(Xhi, Xlo, Whi + 2 * WSZ, Wlo + 2 * WSZ,
                                     bv, (__nv_bfloat16*)vh, (__nv_bfloat16*)vl,
                                     1.0f);

    cudaFuncSetAttribute(swa_mma, cudaFuncAttributeMaxDynamicSharedMemorySize,
                         AT_SMEM);
    swa_mma<<<dim3(SEQ / 64, NHEAD), 128, AT_SMEM>>>(
        (const __nv_bfloat16*)qh, (const __nv_bfloat16*)ql,
        (const __nv_bfloat16*)kh, (const __nv_bfloat16*)kl,
        (const __nv_bfloat16*)vh, (const __nv_bfloat16*)vl, out);
}

// round 5
// speedup vs baseline: 3.0952x; 1.5875x over previous
#include <cuda_runtime.h>
#include <cuda_bf16.h>
#include <math.h>
#include <stdint.h>

#define SEQ    8192
#define HIDDIM 768
#define NHEAD  12
#define HD     64
#define WIN    256

// ---------------- scratch (__device__ globals; allocation-free rule) -------
__device__ __nv_bfloat16 g_Qh[SEQ * HIDDIM];
__device__ __nv_bfloat16 g_Ql[SEQ * HIDDIM];
__device__ __nv_bfloat16 g_Kh[SEQ * HIDDIM];
__device__ __nv_bfloat16 g_Kl[SEQ * HIDDIM];
__device__ __nv_bfloat16 g_Vh[SEQ * HIDDIM];
__device__ __nv_bfloat16 g_Vl[SEQ * HIDDIM];
__device__ __nv_bfloat16 g_Xhi[SEQ * HIDDIM];
__device__ __nv_bfloat16 g_Xlo[SEQ * HIDDIM];
__device__ __nv_bfloat16 g_Wthi[3][HIDDIM * HIDDIM];   // packed [2304][768] K-major
__device__ __nv_bfloat16 g_Wtlo[3][HIDDIM * HIDDIM];

// ---------------- helpers ---------------------------------------------------
__device__ __forceinline__ uint32_t smem_u32(const void* p) {
    uint32_t a;
    asm("{ .reg .u64 t; cvta.to.shared.u64 t, %1; cvt.u32.u64 %0, t; }"
        : "=r"(a) : "l"(p));
    return a;
}
__device__ __forceinline__ void cp16(uint32_t dst, const void* src) {
    asm volatile("cp.async.cg.shared.global [%0], [%1], 16;"
                 :: "r"(dst), "l"(src) : "memory");
}
#define CP_COMMIT()  asm volatile("cp.async.commit_group;" ::: "memory")
#define CP_WAIT1()   asm volatile("cp.async.wait_group 1;" ::: "memory")
#define CP_WAIT0()   asm volatile("cp.async.wait_group 0;" ::: "memory")

__device__ __forceinline__ uint32_t sw128(uint32_t o) {
    return o ^ ((o >> 3) & 0x70);
}
__device__ __forceinline__ float ex2(float x) {
    float y;
    asm("ex2.approx.ftz.f32 %0, %1;" : "=f"(y) : "f"(x));
    return y;
}

#define LDSM_X4(r0, r1, r2, r3, addr) \
    asm volatile("ldmatrix.sync.aligned.m8n8.x4.shared.b16 {%0,%1,%2,%3}, [%4];" \
        : "=r"(r0), "=r"(r1), "=r"(r2), "=r"(r3) : "r"(addr))

#define LDSM_X4_T(r0, r1, r2, r3, addr) \
    asm volatile("ldmatrix.sync.aligned.m8n8.x4.trans.shared.b16 {%0,%1,%2,%3}, [%4];" \
        : "=r"(r0), "=r"(r1), "=r"(r2), "=r"(r3) : "r"(addr))

#define MMA16816(c, a, b0, b1) \
    asm volatile("mma.sync.aligned.m16n8k16.row.col.f32.bf16.bf16.f32 " \
        "{%0,%1,%2,%3}, {%4,%5,%6,%7}, {%8,%9}, {%0,%1,%2,%3};" \
        : "+f"((c)[0]), "+f"((c)[1]), "+f"((c)[2]), "+f"((c)[3]) \
        : "r"((a)[0]), "r"((a)[1]), "r"((a)[2]), "r"((a)[3]), \
          "r"(b0), "r"(b1))

__device__ __forceinline__ void pack_hl(float p0, float p1,
                                        uint32_t& hw, uint32_t& lw) {
    __nv_bfloat16 h0 = __float2bfloat16(p0), h1 = __float2bfloat16(p1);
    hw = (uint32_t)__bfloat16_as_ushort(h0) |
         ((uint32_t)__bfloat16_as_ushort(h1) << 16);
    __nv_bfloat16 l0 = __float2bfloat16(p0 - __bfloat162float(h0));
    __nv_bfloat16 l1 = __float2bfloat16(p1 - __bfloat162float(h1));
    lw = (uint32_t)__bfloat16_as_ushort(l0) |
         ((uint32_t)__bfloat16_as_ushort(l1) << 16);
}

// ---------------- prep kernels ---------------------------------------------
__global__ void convert_x(const float* __restrict__ X,
                          __nv_bfloat16* __restrict__ hi,
                          __nv_bfloat16* __restrict__ lo, int n) {
    int i = blockIdx.x * blockDim.x + threadIdx.x;
    if (i < n) {
        float x = X[i];
        __nv_bfloat16 h = __float2bfloat16(x);
        hi[i] = h;
        lo[i] = __float2bfloat16(x - __bfloat162float(h));
    }
}

// Wz [K][N] row-major -> packed W^T hi/lo [z][N][K]; z = blockIdx.z
__global__ void wt_convert3(const float* __restrict__ W0,
                            const float* __restrict__ W1,
                            const float* __restrict__ W2,
                            __nv_bfloat16* __restrict__ Thi,
                            __nv_bfloat16* __restrict__ Tlo) {
    __shared__ float tile[32][33];
    const int z = blockIdx.z;
    const float* W = (z == 0) ? W0 : (z == 1) ? W1 : W2;
    __nv_bfloat16* th = Thi + (size_t)z * HIDDIM * HIDDIM;
    __nv_bfloat16* tl = Tlo + (size_t)z * HIDDIM * HIDDIM;
    int tx = threadIdx.x, ty = threadIdx.y;   // 32 x 8
    int n0 = blockIdx.x * 32, k0 = blockIdx.y * 32;
    #pragma unroll
    for (int i = 0; i < 4; i++)
        tile[ty + i * 8][tx] = W[(size_t)(k0 + ty + i * 8) * HIDDIM + n0 + tx];
    __syncthreads();
    #pragma unroll
    for (int i = 0; i < 4; i++) {
        float v = tile[tx][ty + i * 8];
        __nv_bfloat16 h = __float2bfloat16(v);
        size_t o = (size_t)(n0 + ty + i * 8) * HIDDIM + k0 + tx;
        th[o] = h;
        tl[o] = __float2bfloat16(v - __bfloat162float(h));
    }
}

// ---------------- fused bf16-split HMMA GEMM (Q|K|V in one grid) ------------
#define KC      64
#define NCHUNK  (HIDDIM / KC)          // 12
#define TBYTES  (128 * 128)
#define BUFB    (4 * TBYTES)
#define GEMM_SMEM (2 * BUFB)           // 131072 B

__global__ __launch_bounds__(256, 1) void gemm_mma_fused(
    const __nv_bfloat16* __restrict__ Ah, const __nv_bfloat16* __restrict__ Al,
    const __nv_bfloat16* __restrict__ Wh, const __nv_bfloat16* __restrict__ Wl,
    const float* __restrict__ bq, const float* __restrict__ bk,
    const float* __restrict__ bv,
    __nv_bfloat16* __restrict__ Qh, __nv_bfloat16* __restrict__ Ql,
    __nv_bfloat16* __restrict__ Kh, __nv_bfloat16* __restrict__ Kl,
    __nv_bfloat16* __restrict__ Vh, __nv_bfloat16* __restrict__ Vl,
    float qscale)
{
    extern __shared__ __align__(1024) char smem[];
    const uint32_t sb = smem_u32(smem);
    const int t = threadIdx.x;
    const int wid = t >> 5, lane = t & 31;
    const int wm = wid >> 1;
    const int wn = wid & 1;
    const int m0 = blockIdx.y * 128;
    const int mat = blockIdx.x / 6;               // 0=Q 1=K 2=V
    const int n0m = (blockIdx.x % 6) * 128;       // col within matrix
    // packed W^T: global row = blockIdx.x*128 + r
    const __nv_bfloat16* Bh = Wh + (size_t)blockIdx.x * 128 * HIDDIM;
    const __nv_bfloat16* Bl = Wl + (size_t)blockIdx.x * 128 * HIDDIM;

    auto load_chunk = [&](int c, int b) {
        const int kk0 = c * KC;
        const uint32_t base = sb + b * BUFB;
        #pragma unroll
        for (int i = 0; i < 4; i++) {
            int cid = t + i * 256;
            int row = cid >> 3, seg = cid & 7;
            uint32_t sw = sw128(row * 128 + seg * 16);
            size_t aoff = (size_t)(m0 + row) * HIDDIM + kk0 + seg * 8;
            size_t boff = (size_t)row * HIDDIM + kk0 + seg * 8;
            cp16(base + sw,              Ah + aoff);
            cp16(base + TBYTES + sw,     Al + aoff);
            cp16(base + 2 * TBYTES + sw, Bh + boff);
            cp16(base + 3 * TBYTES + sw, Bl + boff);
        }
        CP_COMMIT();
    };

    float acc[2][8][4];
    #pragma unroll
    for (int mi = 0; mi < 2; mi++)
        #pragma unroll
        for (int f = 0; f < 8; f++)
            #pragma unroll
            for (int r = 0; r < 4; r++) acc[mi][f][r] = 0.f;

    const int lrow = (lane & 7) + ((lane >> 3) & 1) * 8;
    const int lcol = (lane >> 4) * 16;

    load_chunk(0, 0);
    load_chunk(1, 1);

    for (int c = 0; c < NCHUNK; c++) {
        if (c < NCHUNK - 1) CP_WAIT1(); else CP_WAIT0();
        __syncthreads();

        const uint32_t base = sb + (c & 1) * BUFB;
        const uint32_t baseAh = base;
        const uint32_t baseAl = base + TBYTES;
        const uint32_t baseBh = base + 2 * TBYTES;
        const uint32_t baseBl = base + 3 * TBYTES;

        #pragma unroll
        for (int ks = 0; ks < 4; ks++) {
            uint32_t ah[2][4], al[2][4];
            #pragma unroll
            for (int mi = 0; mi < 2; mi++) {
                uint32_t off = sw128((wm * 32 + mi * 16 + lrow) * 128 +
                                     ks * 32 + lcol);
                LDSM_X4(ah[mi][0], ah[mi][1], ah[mi][2], ah[mi][3], baseAh + off);
                LDSM_X4(al[mi][0], al[mi][1], al[mi][2], al[mi][3], baseAl + off);
            }
            #pragma unroll
            for (int g = 0; g < 4; g++) {
                uint32_t boff = sw128((wn * 64 + g * 16 + lrow) * 128 +
                                      ks * 32 + lcol);
                uint32_t bh[4], bl[4];
                LDSM_X4(bh[0], bh[1], bh[2], bh[3], baseBh + boff);
                LDSM_X4(bl[0], bl[1], bl[2], bl[3], baseBl + boff);
                #pragma unroll
                for (int mi = 0; mi < 2; mi++) {
                    MMA16816(acc[mi][g * 2 + 0], ah[mi], bh[0], bh[2]);
                    MMA16816(acc[mi][g * 2 + 0], ah[mi], bl[0], bl[2]);
                    MMA16816(acc[mi][g * 2 + 0], al[mi], bh[0], bh[2]);
                    MMA16816(acc[mi][g * 2 + 1], ah[mi], bh[1], bh[3]);
                    MMA16816(acc[mi][g * 2 + 1], ah[mi], bl[1], bl[3]);
                    MMA16816(acc[mi][g * 2 + 1], al[mi], bh[1], bh[3]);
                }
            }
        }
        __syncthreads();
        if (c + 2 < NCHUNK) load_chunk(c + 2, c & 1);
    }

    const float* bias = (mat == 0) ? bq : (mat == 1) ? bk : bv;
    __nv_bfloat16* Ohi = (mat == 0) ? Qh : (mat == 1) ? Kh : Vh;
    __nv_bfloat16* Olo = (mat == 0) ? Ql : (mat == 1) ? Kl : Vl;
    const float scale = (mat == 0) ? qscale : 1.0f;

    #pragma unroll
    for (int mi = 0; mi < 2; mi++) {
        const int mrow = m0 + wm * 32 + mi * 16 + (lane >> 2);
        #pragma unroll
        for (int f = 0; f < 8; f++) {
            const int col = n0m + wn * 64 + (f >> 1) * 16 + (f & 1) * 8 +
                            (lane & 3) * 2;
            const float b0 = bias[col], b1 = bias[col + 1];
            float v0 = (acc[mi][f][0] + b0) * scale;
            float v1 = (acc[mi][f][1] + b1) * scale;
            float v2 = (acc[mi][f][2] + b0) * scale;
            float v3 = (acc[mi][f][3] + b1) * scale;
            uint32_t hw0, lw0, hw1, lw1;
            pack_hl(v0, v1, hw0, lw0);
            pack_hl(v2, v3, hw1, lw1);
            *(uint32_t*)(Ohi + (size_t)mrow * HIDDIM + col) = hw0;
            *(uint32_t*)(Olo + (size_t)mrow * HIDDIM + col) = lw0;
            *(uint32_t*)(Ohi + (size_t)(mrow + 8) * HIDDIM + col) = hw1;
            *(uint32_t*)(Olo + (size_t)(mrow + 8) * HIDDIM + col) = lw1;
        }
    }
}

// ---------------------------------------------------------------------------
// Tensor-core sliding-window flash attention with per-warp band skipping.
// ---------------------------------------------------------------------------
#define AT_QOFF   0
#define AT_BUF    16384
#define AT_BUFSZ  32768
#define AT_SMEM   (16384 + 2 * 32768)   // 81920

__global__ __launch_bounds__(128) void swa_mma(
    const __nv_bfloat16* __restrict__ Qh_, const __nv_bfloat16* __restrict__ Ql_,
    const __nv_bfloat16* __restrict__ Kh_, const __nv_bfloat16* __restrict__ Kl_,
    const __nv_bfloat16* __restrict__ Vh_, const __nv_bfloat16* __restrict__ Vl_,
    float* __restrict__ out)
{
    extern __shared__ __align__(1024) char smem[];
    const uint32_t sb = smem_u32(smem);
    const int t = threadIdx.x, lane = t & 31, w = t >> 5;
    const int q0 = blockIdx.x * 64;
    const int h  = blockIdx.y;
    const int cb = h * HD;

    const uint32_t bQh = sb + AT_QOFF, bQl = bQh + 8192;

    auto ld_q = [&]() {
        #pragma unroll
        for (int i = 0; i < 4; i++) {
            int cid = t + i * 128;
            int row = cid >> 3, seg = cid & 7;
            uint32_t sw = sw128(row * 128 + seg * 16);
            size_t g = (size_t)(q0 + row) * HIDDIM + cb + seg * 8;
            cp16(bQh + sw, Qh_ + g);
            cp16(bQl + sw, Ql_ + g);
        }
    };
    auto ld_kv = [&](int kt, int buf) {
        const int kbase = q0 - WIN + kt * 64;
        const uint32_t bb = sb + AT_BUF + buf * AT_BUFSZ;
        #pragma unroll
        for (int i = 0; i < 4; i++) {
            int cid = t + i * 128;
            int row = cid >> 3, seg = cid & 7;
            int kr = kbase + row;
            int cr = ((unsigned)kr < SEQ) ? kr : 0;
            uint32_t sw = sw128(row * 128 + seg * 16);
            size_t g = (size_t)cr * HIDDIM + cb + seg * 8;
            cp16(bb + sw,          Kh_ + g);
            cp16(bb + 8192 + sw,   Kl_ + g);
            cp16(bb + 16384 + sw,  Vh_ + g);
            cp16(bb + 24576 + sw,  Vl_ + g);
        }
    };

    ld_q(); ld_kv(0, 0); CP_COMMIT();
    ld_kv(1, 1); CP_COMMIT();

    const int lrow = (lane & 7) + ((lane >> 3) & 1) * 8;
    const int lcol = (lane >> 4) * 16;

    float oacc[8][4];
    #pragma unroll
    for (int n = 0; n < 8; n++)
        #pragma unroll
        for (int r = 0; r < 4; r++) oacc[n][r] = 0.f;
    float m0r = -1e30f, m1r = -1e30f, l0 = 0.f, l1 = 0.f;

    CP_WAIT1();
    __syncthreads();

    uint32_t qh[4][4], ql[4][4];
    #pragma unroll
    for (int ks = 0; ks < 4; ks++) {
        uint32_t off = sw128((w * 16 + lrow) * 128 + ks * 32 + lcol);
        LDSM_X4(qh[ks][0], qh[ks][1], qh[ks][2], qh[ks][3], bQh + off);
        LDSM_X4(ql[ks][0], ql[ks][1], ql[ks][2], ql[ks][3], bQl + off);
    }

    const int r0q = q0 + w * 16 + (lane >> 2);
    // warp-valid key range (window + sequence bounds)
    const int wklo = max(q0 + w * 16 - WIN, 0);
    const int wkhi = min(q0 + w * 16 + 15 + WIN, SEQ - 1);

    for (int kt = 0; kt < 9; kt++) {
        if (kt) {
            if (kt < 8) CP_WAIT1(); else CP_WAIT0();
            __syncthreads();
        }
        const uint32_t bb = sb + AT_BUF + (kt & 1) * AT_BUFSZ;
        const uint32_t bKh = bb, bKl = bb + 8192;
        const uint32_t bVh = bb + 16384, bVl = bb + 24576;
        const int kbase = q0 - WIN + kt * 64;

        // ---- S = Q K^T (skip n16 groups fully outside warp band) ----
        float sc[8][4];
        #pragma unroll
        for (int n = 0; n < 8; n++)
            #pragma unroll
            for (int r = 0; r < 4; r++) sc[n][r] = -1e30f;

        #pragma unroll
        for (int g = 0; g < 4; g++) {
            const int gk0 = kbase + g * 16;
            if (gk0 + 15 < wklo || gk0 > wkhi) continue;   // warp-uniform
            sc[g * 2 + 0][0] = sc[g * 2 + 0][1] = sc[g * 2 + 0][2] = sc[g * 2 + 0][3] = 0.f;
            sc[g * 2 + 1][0] = sc[g * 2 + 1][1] = sc[g * 2 + 1][2] = sc[g * 2 + 1][3] = 0.f;
            #pragma unroll
            for (int ks = 0; ks < 4; ks++) {
                uint32_t off = sw128((g * 16 + lrow) * 128 + ks * 32 + lcol);
                uint32_t h0, h1, h2, h3, e0, e1, e2, e3;
                LDSM_X4(h0, h1, h2, h3, bKh + off);
                LDSM_X4(e0, e1, e2, e3, bKl + off);
                MMA16816(sc[g * 2 + 0], qh[ks], h0, h2);
                MMA16816(sc[g * 2 + 0], qh[ks], e0, e2);
                MMA16816(sc[g * 2 + 0], ql[ks], h0, h2);
                MMA16816(sc[g * 2 + 1], qh[ks], h1, h3);
                MMA16816(sc[g * 2 + 1], qh[ks], e1, e3);
                MMA16816(sc[g * 2 + 1], ql[ks], h1, h3);
            }
        }

        // ---- mask + online softmax (base-2) ----
        float mx0 = -1e30f, mx1 = -1e30f;
        #pragma unroll
        for (int n = 0; n < 8; n++) {
            const int k0p = kbase + n * 8 + (lane & 3) * 2;
            const int k1p = k0p + 1;
            bool v00 = ((unsigned)k0p < SEQ) && (unsigned)(k0p - r0q + WIN) <= 2 * WIN;
            bool v01 = ((unsigned)k1p < SEQ) && (unsigned)(k1p - r0q + WIN) <= 2 * WIN;
            bool v10 = ((unsigned)k0p < SEQ) && (unsigned)(k0p - (r0q + 8) + WIN) <= 2 * WIN;
            bool v11 = ((unsigned)k1p < SEQ) && (unsigned)(k1p - (r0q + 8) + WIN) <= 2 * WIN;
            if (!v00) sc[n][0] = -1e30f;
            if (!v01) sc[n][1] = -1e30f;
            if (!v10) sc[n][2] = -1e30f;
            if (!v11) sc[n][3] = -1e30f;
            mx0 = fmaxf(mx0, fmaxf(sc[n][0], sc[n][1]));
            mx1 = fmaxf(mx1, fmaxf(sc[n][2], sc[n][3]));
        }
        mx0 = fmaxf(mx0, __shfl_xor_sync(0xffffffffu, mx0, 1));
        mx0 = fmaxf(mx0, __shfl_xor_sync(0xffffffffu, mx0, 2));
        mx1 = fmaxf(mx1, __shfl_xor_sync(0xffffffffu, mx1, 1));
        mx1 = fmaxf(mx1, __shfl_xor_sync(0xffffffffu, mx1, 2));

        const float mn0 = fmaxf(m0r, mx0), mn1 = fmaxf(m1r, mx1);
        const float a0 = ex2(m0r - mn0), a1 = ex2(m1r - mn1);
        m0r = mn0; m1r = mn1;

        float s0 = 0.f, s1 = 0.f;
        #pragma unroll
        for (int n = 0; n < 8; n++) {
            sc[n][0] = ex2(sc[n][0] - mn0);
            sc[n][1] = ex2(sc[n][1] - mn0);
            sc[n][2] = ex2(sc[n][2] - mn1);
            sc[n][3] = ex2(sc[n][3] - mn1);
            s0 += sc[n][0] + sc[n][1];
            s1 += sc[n][2] + sc[n][3];
        }
        s0 += __shfl_xor_sync(0xffffffffu, s0, 1);
        s0 += __shfl_xor_sync(0xffffffffu, s0, 2);
        s1 += __shfl_xor_sync(0xffffffffu, s1, 1);
        s1 += __shfl_xor_sync(0xffffffffu, s1, 2);
        l0 = l0 * a0 + s0;
        l1 = l1 * a1 + s1;
        #pragma unroll
        for (int n = 0; n < 8; n++) {
            oacc[n][0] *= a0; oacc[n][1] *= a0;
            oacc[n][2] *= a1; oacc[n][3] *= a1;
        }

        // ---- repack P into A-fragments (hi/lo) ----
        uint32_t ph[4][4], pl[4][4];
        #pragma unroll
        for (int g = 0; g < 4; g++) {
            pack_hl(sc[2 * g][0],     sc[2 * g][1],     ph[g][0], pl[g][0]);
            pack_hl(sc[2 * g][2],     sc[2 * g][3],     ph[g][1], pl[g][1]);
            pack_hl(sc[2 * g + 1][0], sc[2 * g + 1][1], ph[g][2], pl[g][2]);
            pack_hl(sc[2 * g + 1][2], sc[2 * g + 1][3], ph[g][3], pl[g][3]);
        }

        // ---- O += P V (skip key groups fully outside warp band: P==0) ----
        #pragma unroll
        for (int g = 0; g < 4; g++) {
            const int gk0 = kbase + g * 16;
            if (gk0 + 15 < wklo || gk0 > wkhi) continue;
            #pragma unroll
            for (int t2 = 0; t2 < 4; t2++) {
                uint32_t voff = sw128((g * 16 + (lane & 15)) * 128 +
                                      t2 * 32 + (lane >> 4) * 16);
                uint32_t v0, v1, v2, v3, u0, u1, u2, u3;
                LDSM_X4_T(v0, v1, v2, v3, bVh + voff);
                LDSM_X4_T(u0, u1, u2, u3, bVl + voff);
                MMA16816(oacc[2 * t2 + 0], ph[g], v0, v1);
                MMA16816(oacc[2 * t2 + 0], ph[g], u0, u1);
                MMA16816(oacc[2 * t2 + 0], pl[g], v0, v1);
                MMA16816(oacc[2 * t2 + 1], ph[g], v2, v3);
                MMA16816(oacc[2 * t2 + 1], ph[g], u2, u3);
                MMA16816(oacc[2 * t2 + 1], pl[g], v2, v3);
            }
        }

        __syncthreads();
        if (kt + 2 <= 8) { ld_kv(kt + 2, kt & 1); CP_COMMIT(); }
    }

    // ---- epilogue ----
    const float i0 = 1.f / l0, i1 = 1.f / l1;
    #pragma unroll
    for (int n = 0; n < 8; n++) {
        const int col = cb + n * 8 + (lane & 3) * 2;
        float2 w0, w1;
        w0.x = oacc[n][0] * i0; w0.y = oacc[n][1] * i0;
        w1.x = oacc[n][2] * i1; w1.y = oacc[n][3] * i1;
        *(float2*)(out + (size_t)r0q * HIDDIM + col) = w0;
        *(float2*)(out + (size_t)(r0q + 8) * HIDDIM + col) = w1;
    }
}

// ---------------------------------------------------------------------------
extern "C" void kernel_launch(void* const* d_in, const int* in_sizes, int n_in,
                              void* d_out, int out_size)
{
    const float* X  = (const float*)d_in[0];
    const float* Wq = (const float*)d_in[1];
    const float* bq = (const float*)d_in[2];
    const float* Wk = (const float*)d_in[3];
    const float* bk = (const float*)d_in[4];
    const float* Wv = (const float*)d_in[5];
    const float* bv = (const float*)d_in[6];
    float* out = (float*)d_out;

    void *qh, *ql, *kh, *kl, *vh, *vl, *xh, *xl, *wh, *wl;
    cudaGetSymbolAddress(&qh, g_Qh);  cudaGetSymbolAddress(&ql, g_Ql);
    cudaGetSymbolAddress(&kh, g_Kh);  cudaGetSymbolAddress(&kl, g_Kl);
    cudaGetSymbolAddress(&vh, g_Vh);  cudaGetSymbolAddress(&vl, g_Vl);
    cudaGetSymbolAddress(&xh, g_Xhi); cudaGetSymbolAddress(&xl, g_Xlo);
    cudaGetSymbolAddress(&wh, g_Wthi); cudaGetSymbolAddress(&wl, g_Wtlo);

    __nv_bfloat16* Xhi = (__nv_bfloat16*)xh;
    __nv_bfloat16* Xlo = (__nv_bfloat16*)xl;
    __nv_bfloat16* Whi = (__nv_bfloat16*)wh;
    __nv_bfloat16* Wlo = (__nv_bfloat16*)wl;

    const int nX = SEQ * HIDDIM;
    convert_x<<<(nX + 255) / 256, 256>>>(X, Xhi, Xlo, nX);
    dim3 wtg(HIDDIM / 32, HIDDIM / 32, 3), wtb(32, 8);
    wt_convert3<<<wtg, wtb>>>(Wq, Wk, Wv, Whi, Wlo);

    cudaFuncSetAttribute(gemm_mma_fused,
                         cudaFuncAttributeMaxDynamicSharedMemorySize, GEMM_SMEM);
    const float qscale = 0.125f * 1.4426950408889634f;   // 1/sqrt(64)*log2(e)
    dim3 gg(3 * HIDDIM / 128, SEQ / 128);                // (18, 64)
    gemm_mma_fused<<<gg, 256, GEMM_SMEM>>>(
        Xhi, Xlo, Whi, Wlo, bq, bk, bv,
        (__nv_bfloat16*)qh, (__nv_bfloat16*)ql,
        (__nv_bfloat16*)kh, (__nv_bfloat16*)kl,
        (__nv_bfloat16*)vh, (__nv_bfloat16*)vl, qscale);

    cudaFuncSetAttribute(swa_mma, cudaFuncAttributeMaxDynamicSharedMemorySize,
                         AT_SMEM);
    swa_mma<<<dim3(SEQ / 64, NHEAD), 128, AT_SMEM>>>(
        (const __nv_bfloat16*)qh, (const __nv_bfloat16*)ql,
        (const __nv_bfloat16*)kh, (const __nv_bfloat16*)kl,
        (const __nv_bfloat16*)vh, (const __nv_bfloat16*)vl, out);
}

// round 7
// speedup vs baseline: 3.1731x; 1.0252x over previous
#include <cuda_runtime.h>
#include <cuda_bf16.h>
#include <math.h>
#include <stdint.h>

#define SEQ    8192
#define HIDDIM 768
#define NHEAD  12
#define HD     64
#define WIN    256

// ---------------- scratch (__device__ globals; allocation-free rule) -------
__device__ __nv_bfloat16 g_Qh[SEQ * HIDDIM];
__device__ __nv_bfloat16 g_Ql[SEQ * HIDDIM];
__device__ __nv_bfloat16 g_Kh[SEQ * HIDDIM];
__device__ __nv_bfloat16 g_Kl[SEQ * HIDDIM];
__device__ __nv_bfloat16 g_Vh[SEQ * HIDDIM];
__device__ __nv_bfloat16 g_Vl[SEQ * HIDDIM];
__device__ __nv_bfloat16 g_Xhi[SEQ * HIDDIM];
__device__ __nv_bfloat16 g_Xlo[SEQ * HIDDIM];
__device__ __nv_bfloat16 g_Wthi[3][HIDDIM * HIDDIM];   // packed [2304][768] K-major
__device__ __nv_bfloat16 g_Wtlo[3][HIDDIM * HIDDIM];

// ---------------- helpers ---------------------------------------------------
__device__ __forceinline__ uint32_t smem_u32(const void* p) {
    uint32_t a;
    asm("{ .reg .u64 t; cvta.to.shared.u64 t, %1; cvt.u32.u64 %0, t; }"
        : "=r"(a) : "l"(p));
    return a;
}
__device__ __forceinline__ void cp16(uint32_t dst, const void* src) {
    asm volatile("cp.async.cg.shared.global [%0], [%1], 16;"
                 :: "r"(dst), "l"(src) : "memory");
}
#define CP_COMMIT()  asm volatile("cp.async.commit_group;" ::: "memory")
#define CP_WAIT1()   asm volatile("cp.async.wait_group 1;" ::: "memory")
#define CP_WAIT0()   asm volatile("cp.async.wait_group 0;" ::: "memory")

__device__ __forceinline__ uint32_t sw128(uint32_t o) {
    return o ^ ((o >> 3) & 0x70);
}
__device__ __forceinline__ float ex2(float x) {
    float y;
    asm("ex2.approx.ftz.f32 %0, %1;" : "=f"(y) : "f"(x));
    return y;
}

#define LDSM_X4(r0, r1, r2, r3, addr) \
    asm volatile("ldmatrix.sync.aligned.m8n8.x4.shared.b16 {%0,%1,%2,%3}, [%4];" \
        : "=r"(r0), "=r"(r1), "=r"(r2), "=r"(r3) : "r"(addr))

#define LDSM_X4_T(r0, r1, r2, r3, addr) \
    asm volatile("ldmatrix.sync.aligned.m8n8.x4.trans.shared.b16 {%0,%1,%2,%3}, [%4];" \
        : "=r"(r0), "=r"(r1), "=r"(r2), "=r"(r3) : "r"(addr))

#define MMA16816(c, a, b0, b1) \
    asm volatile("mma.sync.aligned.m16n8k16.row.col.f32.bf16.bf16.f32 " \
        "{%0,%1,%2,%3}, {%4,%5,%6,%7}, {%8,%9}, {%0,%1,%2,%3};" \
        : "+f"((c)[0]), "+f"((c)[1]), "+f"((c)[2]), "+f"((c)[3]) \
        : "r"((a)[0]), "r"((a)[1]), "r"((a)[2]), "r"((a)[3]), \
          "r"(b0), "r"(b1))

__device__ __forceinline__ void pack_hl(float p0, float p1,
                                        uint32_t& hw, uint32_t& lw) {
    __nv_bfloat16 h0 = __float2bfloat16(p0), h1 = __float2bfloat16(p1);
    hw = (uint32_t)__bfloat16_as_ushort(h0) |
         ((uint32_t)__bfloat16_as_ushort(h1) << 16);
    __nv_bfloat16 l0 = __float2bfloat16(p0 - __bfloat162float(h0));
    __nv_bfloat16 l1 = __float2bfloat16(p1 - __bfloat162float(h1));
    lw = (uint32_t)__bfloat16_as_ushort(l0) |
         ((uint32_t)__bfloat16_as_ushort(l1) << 16);
}

// ---------------- prep kernels ---------------------------------------------
__global__ void convert_x(const float* __restrict__ X,
                          __nv_bfloat16* __restrict__ hi,
                          __nv_bfloat16* __restrict__ lo, int n) {
    int i = blockIdx.x * blockDim.x + threadIdx.x;
    if (i < n) {
        float x = X[i];
        __nv_bfloat16 h = __float2bfloat16(x);
        hi[i] = h;
        lo[i] = __float2bfloat16(x - __bfloat162float(h));
    }
}

__global__ void wt_convert3(const float* __restrict__ W0,
                            const float* __restrict__ W1,
                            const float* __restrict__ W2,
                            __nv_bfloat16* __restrict__ Thi,
                            __nv_bfloat16* __restrict__ Tlo) {
    __shared__ float tile[32][33];
    const int z = blockIdx.z;
    const float* W = (z == 0) ? W0 : (z == 1) ? W1 : W2;
    __nv_bfloat16* th = Thi + (size_t)z * HIDDIM * HIDDIM;
    __nv_bfloat16* tl = Tlo + (size_t)z * HIDDIM * HIDDIM;
    int tx = threadIdx.x, ty = threadIdx.y;   // 32 x 8
    int n0 = blockIdx.x * 32, k0 = blockIdx.y * 32;
    #pragma unroll
    for (int i = 0; i < 4; i++)
        tile[ty + i * 8][tx] = W[(size_t)(k0 + ty + i * 8) * HIDDIM + n0 + tx];
    __syncthreads();
    #pragma unroll
    for (int i = 0; i < 4; i++) {
        float v = tile[tx][ty + i * 8];
        __nv_bfloat16 h = __float2bfloat16(v);
        size_t o = (size_t)(n0 + ty + i * 8) * HIDDIM + k0 + tx;
        th[o] = h;
        tl[o] = __float2bfloat16(v - __bfloat162float(h));
    }
}

// ---------------- fused bf16-split HMMA GEMM: 512 thr, 16 warps -------------
#define KC      64
#define NCHUNK  (HIDDIM / KC)          // 12
#define TBYTES  (128 * 128)
#define BUFB    (4 * TBYTES)
#define GEMM_SMEM (2 * BUFB)           // 131072 B

__global__ __launch_bounds__(512, 1) void gemm_mma_fused(
    const __nv_bfloat16* __restrict__ Ah, const __nv_bfloat16* __restrict__ Al,
    const __nv_bfloat16* __restrict__ Wh, const __nv_bfloat16* __restrict__ Wl,
    const float* __restrict__ bq, const float* __restrict__ bk,
    const float* __restrict__ bv,
    __nv_bfloat16* __restrict__ Qh, __nv_bfloat16* __restrict__ Ql,
    __nv_bfloat16* __restrict__ Kh, __nv_bfloat16* __restrict__ Kl,
    __nv_bfloat16* __restrict__ Vh, __nv_bfloat16* __restrict__ Vl,
    float qscale)
{
    extern __shared__ __align__(1024) char smem[];
    const uint32_t sb = smem_u32(smem);
    const int t = threadIdx.x;
    const int wid = t >> 5, lane = t & 31;
    const int wm = wid >> 2;                      // 0..3 -> m = wm*32
    const int wn = wid & 3;                       // 0..3 -> n = wn*32
    const int m0 = blockIdx.y * 128;
    const int mat = blockIdx.x / 6;               // 0=Q 1=K 2=V
    const int n0m = (blockIdx.x % 6) * 128;
    const __nv_bfloat16* Bh = Wh + (size_t)blockIdx.x * 128 * HIDDIM;
    const __nv_bfloat16* Bl = Wl + (size_t)blockIdx.x * 128 * HIDDIM;

    auto load_chunk = [&](int c, int b) {
        const int kk0 = c * KC;
        const uint32_t base = sb + b * BUFB;
        #pragma unroll
        for (int i = 0; i < 2; i++) {
            int cid = t + i * 512;
            int row = cid >> 3, seg = cid & 7;
            uint32_t sw = sw128(row * 128 + seg * 16);
            size_t aoff = (size_t)(m0 + row) * HIDDIM + kk0 + seg * 8;
            size_t boff = (size_t)row * HIDDIM + kk0 + seg * 8;
            cp16(base + sw,              Ah + aoff);
            cp16(base + TBYTES + sw,     Al + aoff);
            cp16(base + 2 * TBYTES + sw, Bh + boff);
            cp16(base + 3 * TBYTES + sw, Bl + boff);
        }
        CP_COMMIT();
    };

    float acc[2][4][4];
    #pragma unroll
    for (int mi = 0; mi < 2; mi++)
        #pragma unroll
        for (int f = 0; f < 4; f++)
            #pragma unroll
            for (int r = 0; r < 4; r++) acc[mi][f][r] = 0.f;

    const int lrow = (lane & 7) + ((lane >> 3) & 1) * 8;
    const int lcol = (lane >> 4) * 16;

    load_chunk(0, 0);
    load_chunk(1, 1);

    for (int c = 0; c < NCHUNK; c++) {
        if (c < NCHUNK - 1) CP_WAIT1(); else CP_WAIT0();
        __syncthreads();

        const uint32_t base = sb + (c & 1) * BUFB;
        const uint32_t baseAh = base;
        const uint32_t baseAl = base + TBYTES;
        const uint32_t baseBh = base + 2 * TBYTES;
        const uint32_t baseBl = base + 3 * TBYTES;

        #pragma unroll
        for (int ks = 0; ks < 4; ks++) {
            uint32_t ah[2][4], al[2][4], bh[2][4], bl[2][4];
            #pragma unroll
            for (int mi = 0; mi < 2; mi++) {
                uint32_t off = sw128((wm * 32 + mi * 16 + lrow) * 128 +
                                     ks * 32 + lcol);
                LDSM_X4(ah[mi][0], ah[mi][1], ah[mi][2], ah[mi][3], baseAh + off);
                LDSM_X4(al[mi][0], al[mi][1], al[mi][2], al[mi][3], baseAl + off);
            }
            #pragma unroll
            for (int g = 0; g < 2; g++) {
                uint32_t boff = sw128((wn * 32 + g * 16 + lrow) * 128 +
                                      ks * 32 + lcol);
                LDSM_X4(bh[g][0], bh[g][1], bh[g][2], bh[g][3], baseBh + boff);
                LDSM_X4(bl[g][0], bl[g][1], bl[g][2], bl[g][3], baseBl + boff);
            }
            // three independent passes: 8 independent MMAs each
            #pragma unroll
            for (int mi = 0; mi < 2; mi++)
                #pragma unroll
                for (int g = 0; g < 2; g++) {
                    MMA16816(acc[mi][g * 2 + 0], ah[mi], bh[g][0], bh[g][2]);
                    MMA16816(acc[mi][g * 2 + 1], ah[mi], bh[g][1], bh[g][3]);
                }
            #pragma unroll
            for (int mi = 0; mi < 2; mi++)
                #pragma unroll
                for (int g = 0; g < 2; g++) {
                    MMA16816(acc[mi][g * 2 + 0], ah[mi], bl[g][0], bl[g][2]);
                    MMA16816(acc[mi][g * 2 + 1], ah[mi], bl[g][1], bl[g][3]);
                }
            #pragma unroll
            for (int mi = 0; mi < 2; mi++)
                #pragma unroll
                for (int g = 0; g < 2; g++) {
                    MMA16816(acc[mi][g * 2 + 0], al[mi], bh[g][0], bh[g][2]);
                    MMA16816(acc[mi][g * 2 + 1], al[mi], bh[g][1], bh[g][3]);
                }
        }
        __syncthreads();
        if (c + 2 < NCHUNK) load_chunk(c + 2, c & 1);
    }

    const float* bias = (mat == 0) ? bq : (mat == 1) ? bk : bv;
    __nv_bfloat16* Ohi = (mat == 0) ? Qh : (mat == 1) ? Kh : Vh;
    __nv_bfloat16* Olo = (mat == 0) ? Ql : (mat == 1) ? Kl : Vl;
    const float scale = (mat == 0) ? qscale : 1.0f;

    #pragma unroll
    for (int mi = 0; mi < 2; mi++) {
        const int mrow = m0 + wm * 32 + mi * 16 + (lane >> 2);
        #pragma unroll
        for (int f = 0; f < 4; f++) {
            const int col = n0m + wn * 32 + (f >> 1) * 16 + (f & 1) * 8 +
                            (lane & 3) * 2;
            const float b0 = bias[col], b1 = bias[col + 1];
            float v0 = (acc[mi][f][0] + b0) * scale;
            float v1 = (acc[mi][f][1] + b1) * scale;
            float v2 = (acc[mi][f][2] + b0) * scale;
            float v3 = (acc[mi][f][3] + b1) * scale;
            uint32_t hw0, lw0, hw1, lw1;
            pack_hl(v0, v1, hw0, lw0);
            pack_hl(v2, v3, hw1, lw1);
            *(uint32_t*)(Ohi + (size_t)mrow * HIDDIM + col) = hw0;
            *(uint32_t*)(Olo + (size_t)mrow * HIDDIM + col) = lw0;
            *(uint32_t*)(Ohi + (size_t)(mrow + 8) * HIDDIM + col) = hw1;
            *(uint32_t*)(Olo + (size_t)(mrow + 8) * HIDDIM + col) = lw1;
        }
    }
}

// ---------------------------------------------------------------------------
// Tensor-core sliding-window flash attention.
// Smem overlay: Q region (16KB) is reused as part of KV buffer 1 after the Q
// fragments are register-resident -> 64KB total -> 3 CTAs/SM.
// Layout: [0,32K) = KV buf1 (Q lives at [0,16K) during startup), [32K,64K) = buf0.
// ---------------------------------------------------------------------------
#define AT_BUFSZ  32768
#define AT_SMEM   65536

__global__ __launch_bounds__(128, 3) void swa_mma(
    const __nv_bfloat16* __restrict__ Qh_, const __nv_bfloat16* __restrict__ Ql_,
    const __nv_bfloat16* __restrict__ Kh_, const __nv_bfloat16* __restrict__ Kl_,
    const __nv_bfloat16* __restrict__ Vh_, const __nv_bfloat16* __restrict__ Vl_,
    float* __restrict__ out)
{
    extern __shared__ __align__(1024) char smem[];
    const uint32_t sb = smem_u32(smem);
    const int t = threadIdx.x, lane = t & 31, w = t >> 5;
    const int q0 = blockIdx.x * 64;
    const int h  = blockIdx.y;
    const int cb = h * HD;

    const uint32_t bQh = sb, bQl = sb + 8192;     // inside buf1 region

    auto ld_q = [&]() {
        #pragma unroll
        for (int i = 0; i < 4; i++) {
            int cid = t + i * 128;
            int row = cid >> 3, seg = cid & 7;
            uint32_t sw = sw128(row * 128 + seg * 16);
            size_t g = (size_t)(q0 + row) * HIDDIM + cb + seg * 8;
            cp16(bQh + sw, Qh_ + g);
            cp16(bQl + sw, Ql_ + g);
        }
    };
    auto ld_kv = [&](int kt, int buf) {
        const int kbase = q0 - WIN + kt * 64;
        const uint32_t bb = sb + (buf ? 0 : AT_BUFSZ);
        #pragma unroll
        for (int i = 0; i < 4; i++) {
            int cid = t + i * 128;
            int row = cid >> 3, seg = cid & 7;
            int kr = kbase + row;
            int cr = ((unsigned)kr < SEQ) ? kr : 0;
            uint32_t sw = sw128(row * 128 + seg * 16);
            size_t g = (size_t)cr * HIDDIM + cb + seg * 8;
            cp16(bb + sw,          Kh_ + g);
            cp16(bb + 8192 + sw,   Kl_ + g);
            cp16(bb + 16384 + sw,  Vh_ + g);
            cp16(bb + 24576 + sw,  Vl_ + g);
        }
    };

    ld_q(); CP_COMMIT();
    ld_kv(0, 0); CP_COMMIT();                     // buf0: no overlap with Q
    CP_WAIT0();
    __syncthreads();

    const int lrow = (lane & 7) + ((lane >> 3) & 1) * 8;
    const int lcol = (lane >> 4) * 16;

    // Q fragments (register-resident)
    uint32_t qh[4][4], ql[4][4];
    #pragma unroll
    for (int ks = 0; ks < 4; ks++) {
        uint32_t off = sw128((w * 16 + lrow) * 128 + ks * 32 + lcol);
        LDSM_X4(qh[ks][0], qh[ks][1], qh[ks][2], qh[ks][3], bQh + off);
        LDSM_X4(ql[ks][0], ql[ks][1], ql[ks][2], ql[ks][3], bQl + off);
    }
    __syncthreads();                              // all warps done reading Q
    ld_kv(1, 1); CP_COMMIT();                     // overlays Q region (safe now)

    float oacc[8][4];
    #pragma unroll
    for (int n = 0; n < 8; n++)
        #pragma unroll
        for (int r = 0; r < 4; r++) oacc[n][r] = 0.f;
    float m0r = -1e30f, m1r = -1e30f, l0 = 0.f, l1 = 0.f;

    const int r0q = q0 + w * 16 + (lane >> 2);
    const int wklo = max(q0 + w * 16 - WIN, 0);
    const int wkhi = min(q0 + w * 16 + 15 + WIN, SEQ - 1);

    for (int kt = 0; kt < 9; kt++) {
        if (kt) {
            if (kt < 8) CP_WAIT1(); else CP_WAIT0();
            __syncthreads();
        }
        const uint32_t bb = sb + ((kt & 1) ? 0 : AT_BUFSZ);
        const uint32_t bKh = bb, bKl = bb + 8192;
        const uint32_t bVh = bb + 16384, bVl = bb + 24576;
        const int kbase = q0 - WIN + kt * 64;

        // ---- S = Q K^T (skip n16 groups fully outside warp band) ----
        float sc[8][4];
        #pragma unroll
        for (int n = 0; n < 8; n++)
            #pragma unroll
            for (int r = 0; r < 4; r++) sc[n][r] = -1e30f;

        #pragma unroll
        for (int g = 0; g < 4; g++) {
            const int gk0 = kbase + g * 16;
            if (gk0 + 15 < wklo || gk0 > wkhi) continue;
            sc[g * 2 + 0][0] = sc[g * 2 + 0][1] = sc[g * 2 + 0][2] = sc[g * 2 + 0][3] = 0.f;
            sc[g * 2 + 1][0] = sc[g * 2 + 1][1] = sc[g * 2 + 1][2] = sc[g * 2 + 1][3] = 0.f;
            #pragma unroll
            for (int ks = 0; ks < 4; ks++) {
                uint32_t off = sw128((g * 16 + lrow) * 128 + ks * 32 + lcol);
                uint32_t h0, h1, h2, h3, e0, e1, e2, e3;
                LDSM_X4(h0, h1, h2, h3, bKh + off);
                LDSM_X4(e0, e1, e2, e3, bKl + off);
                MMA16816(sc[g * 2 + 0], qh[ks], h0, h2);
                MMA16816(sc[g * 2 + 0], qh[ks], e0, e2);
                MMA16816(sc[g * 2 + 0], ql[ks], h0, h2);
                MMA16816(sc[g * 2 + 1], qh[ks], h1, h3);
                MMA16816(sc[g * 2 + 1], qh[ks], e1, e3);
                MMA16816(sc[g * 2 + 1], ql[ks], h1, h3);
            }
        }

        // ---- mask + online softmax (base-2) ----
        float mx0 = -1e30f, mx1 = -1e30f;
        #pragma unroll
        for (int n = 0; n < 8; n++) {
            const int k0p = kbase + n * 8 + (lane & 3) * 2;
            const int k1p = k0p + 1;
            bool v00 = ((unsigned)k0p < SEQ) && (unsigned)(k0p - r0q + WIN) <= 2 * WIN;
            bool v01 = ((unsigned)k1p < SEQ) && (unsigned)(k1p - r0q + WIN) <= 2 * WIN;
            bool v10 = ((unsigned)k0p < SEQ) && (unsigned)(k0p - (r0q + 8) + WIN) <= 2 * WIN;
            bool v11 = ((unsigned)k1p < SEQ) && (unsigned)(k1p - (r0q + 8) + WIN) <= 2 * WIN;
            if (!v00) sc[n][0] = -1e30f;
            if (!v01) sc[n][1] = -1e30f;
            if (!v10) sc[n][2] = -1e30f;
            if (!v11) sc[n][3] = -1e30f;
            mx0 = fmaxf(mx0, fmaxf(sc[n][0], sc[n][1]));
            mx1 = fmaxf(mx1, fmaxf(sc[n][2], sc[n][3]));
        }
        mx0 = fmaxf(mx0, __shfl_xor_sync(0xffffffffu, mx0, 1));
        mx0 = fmaxf(mx0, __shfl_xor_sync(0xffffffffu, mx0, 2));
        mx1 = fmaxf(mx1, __shfl_xor_sync(0xffffffffu, mx1, 1));
        mx1 = fmaxf(mx1, __shfl_xor_sync(0xffffffffu, mx1, 2));

        const float mn0 = fmaxf(m0r, mx0), mn1 = fmaxf(m1r, mx1);
        const float a0 = ex2(m0r - mn0), a1 = ex2(m1r - mn1);
        m0r = mn0; m1r = mn1;

        float s0 = 0.f, s1 = 0.f;
        #pragma unroll
        for (int n = 0; n < 8; n++) {
            sc[n][0] = ex2(sc[n][0] - mn0);
            sc[n][1] = ex2(sc[n][1] - mn0);
            sc[n][2] = ex2(sc[n][2] - mn1);
            sc[n][3] = ex2(sc[n][3] - mn1);
            s0 += sc[n][0] + sc[n][1];
            s1 += sc[n][2] + sc[n][3];
        }
        s0 += __shfl_xor_sync(0xffffffffu, s0, 1);
        s0 += __shfl_xor_sync(0xffffffffu, s0, 2);
        s1 += __shfl_xor_sync(0xffffffffu, s1, 1);
        s1 += __shfl_xor_sync(0xffffffffu, s1, 2);
        l0 = l0 * a0 + s0;
        l1 = l1 * a1 + s1;
        #pragma unroll
        for (int n = 0; n < 8; n++) {
            oacc[n][0] *= a0; oacc[n][1] *= a0;
            oacc[n][2] *= a1; oacc[n][3] *= a1;
        }

        // ---- repack P into A-fragments (hi/lo) ----
        uint32_t ph[4][4], pl[4][4];
        #pragma unroll
        for (int g = 0; g < 4; g++) {
            pack_hl(sc[2 * g][0],     sc[2 * g][1],     ph[g][0], pl[g][0]);
            pack_hl(sc[2 * g][2],     sc[2 * g][3],     ph[g][1], pl[g][1]);
            pack_hl(sc[2 * g + 1][0], sc[2 * g + 1][1], ph[g][2], pl[g][2]);
            pack_hl(sc[2 * g + 1][2], sc[2 * g + 1][3], ph[g][3], pl[g][3]);
        }

        // ---- O += P V (skip key groups fully outside warp band) ----
        #pragma unroll
        for (int g = 0; g < 4; g++) {
            const int gk0 = kbase + g * 16;
            if (gk0 + 15 < wklo || gk0 > wkhi) continue;
            #pragma unroll
            for (int t2 = 0; t2 < 4; t2++) {
                uint32_t voff = sw128((g * 16 + (lane & 15)) * 128 +
                                      t2 * 32 + (lane >> 4) * 16);
                uint32_t v0, v1, v2, v3, u0, u1, u2, u3;
                LDSM_X4_T(v0, v1, v2, v3, bVh + voff);
                LDSM_X4_T(u0, u1, u2, u3, bVl + voff);
                MMA16816(oacc[2 * t2 + 0], ph[g], v0, v1);
                MMA16816(oacc[2 * t2 + 0], ph[g], u0, u1);
                MMA16816(oacc[2 * t2 + 0], pl[g], v0, v1);
                MMA16816(oacc[2 * t2 + 1], ph[g], v2, v3);
                MMA16816(oacc[2 * t2 + 1], ph[g], u2, u3);
                MMA16816(oacc[2 * t2 + 1], pl[g], v2, v3);
            }
        }

        __syncthreads();
        if (kt + 2 <= 8) { ld_kv(kt + 2, kt & 1); CP_COMMIT(); }
    }

    // ---- epilogue ----
    const float i0 = 1.f / l0, i1 = 1.f / l1;
    #pragma unroll
    for (int n = 0; n < 8; n++) {
        const int col = cb + n * 8 + (lane & 3) * 2;
        float2 w0, w1;
        w0.x = oacc[n][0] * i0; w0.y = oacc[n][1] * i0;
        w1.x = oacc[n][2] * i1; w1.y = oacc[n][3] * i1;
        *(float2*)(out + (size_t)r0q * HIDDIM + col) = w0;
        *(float2*)(out + (size_t)(r0q + 8) * HIDDIM + col) = w1;
    }
}

// ---------------------------------------------------------------------------
extern "C" void kernel_launch(void* const* d_in, const int* in_sizes, int n_in,
                              void* d_out, int out_size)
{
    const float* X  = (const float*)d_in[0];
    const float* Wq = (const float*)d_in[1];
    const float* bq = (const float*)d_in[2];
    const float* Wk = (const float*)d_in[3];
    const float* bk = (const float*)d_in[4];
    const float* Wv = (const float*)d_in[5];
    const float* bv = (const float*)d_in[6];
    float* out = (float*)d_out;

    void *qh, *ql, *kh, *kl, *vh, *vl, *xh, *xl, *wh, *wl;
    cudaGetSymbolAddress(&qh, g_Qh);  cudaGetSymbolAddress(&ql, g_Ql);
    cudaGetSymbolAddress(&kh, g_Kh);  cudaGetSymbolAddress(&kl, g_Kl);
    cudaGetSymbolAddress(&vh, g_Vh);  cudaGetSymbolAddress(&vl, g_Vl);
    cudaGetSymbolAddress(&xh, g_Xhi); cudaGetSymbolAddress(&xl, g_Xlo);
    cudaGetSymbolAddress(&wh, g_Wthi); cudaGetSymbolAddress(&wl, g_Wtlo);

    __nv_bfloat16* Xhi = (__nv_bfloat16*)xh;
    __nv_bfloat16* Xlo = (__nv_bfloat16*)xl;
    __nv_bfloat16* Whi = (__nv_bfloat16*)wh;
    __nv_bfloat16* Wlo = (__nv_bfloat16*)wl;

    const int nX = SEQ * HIDDIM;
    convert_x<<<(nX + 255) / 256, 256>>>(X, Xhi, Xlo, nX);
    dim3 wtg(HIDDIM / 32, HIDDIM / 32, 3), wtb(32, 8);
    wt_convert3<<<wtg, wtb>>>(Wq, Wk, Wv, Whi, Wlo);

    cudaFuncSetAttribute(gemm_mma_fused,
                         cudaFuncAttributeMaxDynamicSharedMemorySize, GEMM_SMEM);
    const float qscale = 0.125f * 1.4426950408889634f;   // 1/sqrt(64)*log2(e)
    dim3 gg(3 * HIDDIM / 128, SEQ / 128);                // (18, 64)
    gemm_mma_fused<<<gg, 512, GEMM_SMEM>>>(
        Xhi, Xlo, Whi, Wlo, bq, bk, bv,
        (__nv_bfloat16*)qh, (__nv_bfloat16*)ql,
        (__nv_bfloat16*)kh, (__nv_bfloat16*)kl,
        (__nv_bfloat16*)vh, (__nv_bfloat16*)vl, qscale);

    cudaFuncSetAttribute(swa_mma, cudaFuncAttributeMaxDynamicSharedMemorySize,
                         AT_SMEM);
    swa_mma<<<dim3(SEQ / 64, NHEAD), 128, AT_SMEM>>>(
        (const __nv_bfloat16*)qh, (const __nv_bfloat16*)ql,
        (const __nv_bfloat16*)kh, (const __nv_bfloat16*)kl,
        (const __nv_bfloat16*)vh, (const __nv_bfloat16*)vl, out);
}

// round 8
// speedup vs baseline: 3.4330x; 1.0819x over previous
#include <cuda_runtime.h>
#include <cuda_bf16.h>
#include <math.h>
#include <stdint.h>

#define SEQ    8192
#define HIDDIM 768
#define NHEAD  12
#define HD     64
#define WIN    256

// ---------------- scratch (__device__ globals; allocation-free rule) -------
__device__ __nv_bfloat16 g_Qh[SEQ * HIDDIM];
__device__ __nv_bfloat16 g_Ql[SEQ * HIDDIM];
__device__ __nv_bfloat16 g_Kh[SEQ * HIDDIM];
__device__ __nv_bfloat16 g_Kl[SEQ * HIDDIM];
__device__ __nv_bfloat16 g_Vh[SEQ * HIDDIM];
__device__ __nv_bfloat16 g_Vl[SEQ * HIDDIM];
__device__ __nv_bfloat16 g_Xhi[SEQ * HIDDIM];
__device__ __nv_bfloat16 g_Xlo[SEQ * HIDDIM];
__device__ __nv_bfloat16 g_Wthi[3][HIDDIM * HIDDIM];   // packed [2304][768] K-major
__device__ __nv_bfloat16 g_Wtlo[3][HIDDIM * HIDDIM];

// ---------------- helpers ---------------------------------------------------
__device__ __forceinline__ uint32_t smem_u32(const void* p) {
    uint32_t a;
    asm("{ .reg .u64 t; cvta.to.shared.u64 t, %1; cvt.u32.u64 %0, t; }"
        : "=r"(a) : "l"(p));
    return a;
}
__device__ __forceinline__ void cp16(uint32_t dst, const void* src) {
    asm volatile("cp.async.cg.shared.global [%0], [%1], 16;"
                 :: "r"(dst), "l"(src) : "memory");
}
#define CP_COMMIT()  asm volatile("cp.async.commit_group;" ::: "memory")
#define CP_WAIT1()   asm volatile("cp.async.wait_group 1;" ::: "memory")
#define CP_WAIT0()   asm volatile("cp.async.wait_group 0;" ::: "memory")

__device__ __forceinline__ uint32_t sw128(uint32_t o) {
    return o ^ ((o >> 3) & 0x70);
}
__device__ __forceinline__ float ex2(float x) {
    float y;
    asm("ex2.approx.ftz.f32 %0, %1;" : "=f"(y) : "f"(x));
    return y;
}

#define LDSM_X4(r0, r1, r2, r3, addr) \
    asm volatile("ldmatrix.sync.aligned.m8n8.x4.shared.b16 {%0,%1,%2,%3}, [%4];" \
        : "=r"(r0), "=r"(r1), "=r"(r2), "=r"(r3) : "r"(addr))

#define LDSM_X4_T(r0, r1, r2, r3, addr) \
    asm volatile("ldmatrix.sync.aligned.m8n8.x4.trans.shared.b16 {%0,%1,%2,%3}, [%4];" \
        : "=r"(r0), "=r"(r1), "=r"(r2), "=r"(r3) : "r"(addr))

#define MMA16816(c, a, b0, b1) \
    asm volatile("mma.sync.aligned.m16n8k16.row.col.f32.bf16.bf16.f32 " \
        "{%0,%1,%2,%3}, {%4,%5,%6,%7}, {%8,%9}, {%0,%1,%2,%3};" \
        : "+f"((c)[0]), "+f"((c)[1]), "+f"((c)[2]), "+f"((c)[3]) \
        : "r"((a)[0]), "r"((a)[1]), "r"((a)[2]), "r"((a)[3]), \
          "r"(b0), "r"(b1))

__device__ __forceinline__ void pack_hl(float p0, float p1,
                                        uint32_t& hw, uint32_t& lw) {
    __nv_bfloat16 h0 = __float2bfloat16(p0), h1 = __float2bfloat16(p1);
    hw = (uint32_t)__bfloat16_as_ushort(h0) |
         ((uint32_t)__bfloat16_as_ushort(h1) << 16);
    __nv_bfloat16 l0 = __float2bfloat16(p0 - __bfloat162float(h0));
    __nv_bfloat16 l1 = __float2bfloat16(p1 - __bfloat162float(h1));
    lw = (uint32_t)__bfloat16_as_ushort(l0) |
         ((uint32_t)__bfloat16_as_ushort(l1) << 16);
}

// ---------------- prep kernels ---------------------------------------------
__global__ void convert_x4(const float4* __restrict__ X,
                           uint2* __restrict__ hi,
                           uint2* __restrict__ lo, int n4) {
    int i = blockIdx.x * blockDim.x + threadIdx.x;
    if (i < n4) {
        float4 x = X[i];
        uint32_t h0, l0, h1, l1;
        pack_hl(x.x, x.y, h0, l0);
        pack_hl(x.z, x.w, h1, l1);
        hi[i] = make_uint2(h0, h1);
        lo[i] = make_uint2(l0, l1);
    }
}

__global__ void wt_convert3(const float* __restrict__ W0,
                            const float* __restrict__ W1,
                            const float* __restrict__ W2,
                            __nv_bfloat16* __restrict__ Thi,
                            __nv_bfloat16* __restrict__ Tlo) {
    __shared__ float tile[32][33];
    const int z = blockIdx.z;
    const float* W = (z == 0) ? W0 : (z == 1) ? W1 : W2;
    __nv_bfloat16* th = Thi + (size_t)z * HIDDIM * HIDDIM;
    __nv_bfloat16* tl = Tlo + (size_t)z * HIDDIM * HIDDIM;
    int tx = threadIdx.x, ty = threadIdx.y;   // 32 x 8
    int n0 = blockIdx.x * 32, k0 = blockIdx.y * 32;
    #pragma unroll
    for (int i = 0; i < 4; i++)
        tile[ty + i * 8][tx] = W[(size_t)(k0 + ty + i * 8) * HIDDIM + n0 + tx];
    __syncthreads();
    #pragma unroll
    for (int i = 0; i < 4; i++) {
        float v = tile[tx][ty + i * 8];
        __nv_bfloat16 h = __float2bfloat16(v);
        size_t o = (size_t)(n0 + ty + i * 8) * HIDDIM + k0 + tx;
        th[o] = h;
        tl[o] = __float2bfloat16(v - __bfloat162float(h));
    }
}

// ---------------- fused bf16-split HMMA GEMM: 512 thr, 3-stage --------------
#define KC      64
#define NCHUNK  (HIDDIM / KC)          // 12
#define TBYTES  (128 * 128)
#define BUFB    (4 * TBYTES)           // 64 KB per stage
#define GEMM_SMEM (3 * BUFB)           // 196608 B

__global__ __launch_bounds__(512, 1) void gemm_mma_fused(
    const __nv_bfloat16* __restrict__ Ah, const __nv_bfloat16* __restrict__ Al,
    const __nv_bfloat16* __restrict__ Wh, const __nv_bfloat16* __restrict__ Wl,
    const float* __restrict__ bq, const float* __restrict__ bk,
    const float* __restrict__ bv,
    __nv_bfloat16* __restrict__ Qh, __nv_bfloat16* __restrict__ Ql,
    __nv_bfloat16* __restrict__ Kh, __nv_bfloat16* __restrict__ Kl,
    __nv_bfloat16* __restrict__ Vh, __nv_bfloat16* __restrict__ Vl,
    float qscale)
{
    extern __shared__ __align__(1024) char smem[];
    const uint32_t sb = smem_u32(smem);
    const int t = threadIdx.x;
    const int wid = t >> 5, lane = t & 31;
    const int wm = wid >> 2;                      // 0..3 -> m = wm*32
    const int wn = wid & 3;                       // 0..3 -> n = wn*32
    const int m0 = blockIdx.y * 128;
    const int mat = blockIdx.x / 6;               // 0=Q 1=K 2=V
    const int n0m = (blockIdx.x % 6) * 128;
    const __nv_bfloat16* Bh = Wh + (size_t)blockIdx.x * 128 * HIDDIM;
    const __nv_bfloat16* Bl = Wl + (size_t)blockIdx.x * 128 * HIDDIM;

    auto load_chunk = [&](int c, int b) {
        const int kk0 = c * KC;
        const uint32_t base = sb + b * BUFB;
        #pragma unroll
        for (int i = 0; i < 2; i++) {
            int cid = t + i * 512;
            int row = cid >> 3, seg = cid & 7;
            uint32_t sw = sw128(row * 128 + seg * 16);
            size_t aoff = (size_t)(m0 + row) * HIDDIM + kk0 + seg * 8;
            size_t boff = (size_t)row * HIDDIM + kk0 + seg * 8;
            cp16(base + sw,              Ah + aoff);
            cp16(base + TBYTES + sw,     Al + aoff);
            cp16(base + 2 * TBYTES + sw, Bh + boff);
            cp16(base + 3 * TBYTES + sw, Bl + boff);
        }
        CP_COMMIT();
    };

    float acc[2][4][4];
    #pragma unroll
    for (int mi = 0; mi < 2; mi++)
        #pragma unroll
        for (int f = 0; f < 4; f++)
            #pragma unroll
            for (int r = 0; r < 4; r++) acc[mi][f][r] = 0.f;

    const int lrow = (lane & 7) + ((lane >> 3) & 1) * 8;
    const int lcol = (lane >> 4) * 16;
    // sw128(row*128 + B) = row*128 + (B ^ ((row&7)<<4)) for B < 128,
    // row&7 == lrow&7 here (tile-row strides are multiples of 8).
    const uint32_t xa = (uint32_t)((lrow & 7) << 4);
    uint32_t kx[4];
    #pragma unroll
    for (int ks = 0; ks < 4; ks++) kx[ks] = ((uint32_t)(ks * 32 + lcol)) ^ xa;

    load_chunk(0, 0);
    load_chunk(1, 1);

    int bufc = 0, bufl = 2;
    for (int c = 0; c < NCHUNK; c++) {
        if (c < NCHUNK - 1) CP_WAIT1(); else CP_WAIT0();
        __syncthreads();
        if (c + 2 < NCHUNK) {                     // issue BEFORE compute
            load_chunk(c + 2, bufl);
            bufl = (bufl == 2) ? 0 : bufl + 1;
        }

        const uint32_t base = sb + bufc * BUFB;
        bufc = (bufc == 2) ? 0 : bufc + 1;
        const uint32_t baseAh = base;
        const uint32_t baseAl = base + TBYTES;
        const uint32_t baseBh = base + 2 * TBYTES;
        const uint32_t baseBl = base + 3 * TBYTES;
        const uint32_t arow = (uint32_t)(wm * 32 + lrow) * 128;
        const uint32_t brow = (uint32_t)(wn * 32 + lrow) * 128;

        #pragma unroll
        for (int ks = 0; ks < 4; ks++) {
            uint32_t ah[2][4], al[2][4], bh[2][4], bl[2][4];
            #pragma unroll
            for (int mi = 0; mi < 2; mi++) {
                uint32_t off = arow + mi * 2048 + kx[ks];
                LDSM_X4(ah[mi][0], ah[mi][1], ah[mi][2], ah[mi][3], baseAh + off);
                LDSM_X4(al[mi][0], al[mi][1], al[mi][2], al[mi][3], baseAl + off);
            }
            #pragma unroll
            for (int g = 0; g < 2; g++) {
                uint32_t boff = brow + g * 2048 + kx[ks];
                LDSM_X4(bh[g][0], bh[g][1], bh[g][2], bh[g][3], baseBh + boff);
                LDSM_X4(bl[g][0], bl[g][1], bl[g][2], bl[g][3], baseBl + boff);
            }
            #pragma unroll
            for (int mi = 0; mi < 2; mi++)
                #pragma unroll
                for (int g = 0; g < 2; g++) {
                    MMA16816(acc[mi][g * 2 + 0], ah[mi], bh[g][0], bh[g][2]);
                    MMA16816(acc[mi][g * 2 + 1], ah[mi], bh[g][1], bh[g][3]);
                }
            #pragma unroll
            for (int mi = 0; mi < 2; mi++)
                #pragma unroll
                for (int g = 0; g < 2; g++) {
                    MMA16816(acc[mi][g * 2 + 0], ah[mi], bl[g][0], bl[g][2]);
                    MMA16816(acc[mi][g * 2 + 1], ah[mi], bl[g][1], bl[g][3]);
                }
            #pragma unroll
            for (int mi = 0; mi < 2; mi++)
                #pragma unroll
                for (int g = 0; g < 2; g++) {
                    MMA16816(acc[mi][g * 2 + 0], al[mi], bh[g][0], bh[g][2]);
                    MMA16816(acc[mi][g * 2 + 1], al[mi], bh[g][1], bh[g][3]);
                }
        }
        // no trailing sync: next iter's top sync covers buffer reuse (depth 3)
    }

    const float* bias = (mat == 0) ? bq : (mat == 1) ? bk : bv;
    __nv_bfloat16* Ohi = (mat == 0) ? Qh : (mat == 1) ? Kh : Vh;
    __nv_bfloat16* Olo = (mat == 0) ? Ql : (mat == 1) ? Kl : Vl;
    const float scale = (mat == 0) ? qscale : 1.0f;

    #pragma unroll
    for (int mi = 0; mi < 2; mi++) {
        const int mrow = m0 + wm * 32 + mi * 16 + (lane >> 2);
        #pragma unroll
        for (int f = 0; f < 4; f++) {
            const int col = n0m + wn * 32 + (f >> 1) * 16 + (f & 1) * 8 +
                            (lane & 3) * 2;
            const float b0 = bias[col], b1 = bias[col + 1];
            float v0 = (acc[mi][f][0] + b0) * scale;
            float v1 = (acc[mi][f][1] + b1) * scale;
            float v2 = (acc[mi][f][2] + b0) * scale;
            float v3 = (acc[mi][f][3] + b1) * scale;
            uint32_t hw0, lw0, hw1, lw1;
            pack_hl(v0, v1, hw0, lw0);
            pack_hl(v2, v3, hw1, lw1);
            *(uint32_t*)(Ohi + (size_t)mrow * HIDDIM + col) = hw0;
            *(uint32_t*)(Olo + (size_t)mrow * HIDDIM + col) = lw0;
            *(uint32_t*)(Ohi + (size_t)(mrow + 8) * HIDDIM + col) = hw1;
            *(uint32_t*)(Olo + (size_t)(mrow + 8) * HIDDIM + col) = lw1;
        }
    }
}

// ---------------------------------------------------------------------------
// Tensor-core sliding-window flash attention (overlayed smem, 3 CTAs/SM).
// ---------------------------------------------------------------------------
#define AT_BUFSZ  32768
#define AT_SMEM   65536

__global__ __launch_bounds__(128, 3) void swa_mma(
    const __nv_bfloat16* __restrict__ Qh_, const __nv_bfloat16* __restrict__ Ql_,
    const __nv_bfloat16* __restrict__ Kh_, const __nv_bfloat16* __restrict__ Kl_,
    const __nv_bfloat16* __restrict__ Vh_, const __nv_bfloat16* __restrict__ Vl_,
    float* __restrict__ out)
{
    extern __shared__ __align__(1024) char smem[];
    const uint32_t sb = smem_u32(smem);
    const int t = threadIdx.x, lane = t & 31, w = t >> 5;
    const int q0 = blockIdx.x * 64;
    const int h  = blockIdx.y;
    const int cb = h * HD;

    const uint32_t bQh = sb, bQl = sb + 8192;     // inside buf1 region

    auto ld_q = [&]() {
        #pragma unroll
        for (int i = 0; i < 4; i++) {
            int cid = t + i * 128;
            int row = cid >> 3, seg = cid & 7;
            uint32_t sw = sw128(row * 128 + seg * 16);
            size_t g = (size_t)(q0 + row) * HIDDIM + cb + seg * 8;
            cp16(bQh + sw, Qh_ + g);
            cp16(bQl + sw, Ql_ + g);
        }
    };
    auto ld_kv = [&](int kt, int buf) {
        const int kbase = q0 - WIN + kt * 64;
        const uint32_t bb = sb + (buf ? 0 : AT_BUFSZ);
        #pragma unroll
        for (int i = 0; i < 4; i++) {
            int cid = t + i * 128;
            int row = cid >> 3, seg = cid & 7;
            int kr = kbase + row;
            int cr = ((unsigned)kr < SEQ) ? kr : 0;
            uint32_t sw = sw128(row * 128 + seg * 16);
            size_t g = (size_t)cr * HIDDIM + cb + seg * 8;
            cp16(bb + sw,          Kh_ + g);
            cp16(bb + 8192 + sw,   Kl_ + g);
            cp16(bb + 16384 + sw,  Vh_ + g);
            cp16(bb + 24576 + sw,  Vl_ + g);
        }
    };

    ld_q(); CP_COMMIT();
    ld_kv(0, 0); CP_COMMIT();                     // buf0: no overlap with Q
    CP_WAIT0();
    __syncthreads();

    const int lrow = (lane & 7) + ((lane >> 3) & 1) * 8;
    const int lcol = (lane >> 4) * 16;
    const uint32_t xa = (uint32_t)((lrow & 7) << 4);
    uint32_t kx[4];
    #pragma unroll
    for (int ks = 0; ks < 4; ks++) kx[ks] = ((uint32_t)(ks * 32 + lcol)) ^ xa;
    const uint32_t krow = (uint32_t)lrow * 128;

    const int vrow = lane & 15;
    const uint32_t xv = (uint32_t)((vrow & 7) << 4);
    uint32_t vx[4];
    #pragma unroll
    for (int t2 = 0; t2 < 4; t2++)
        vx[t2] = ((uint32_t)(t2 * 32 + (lane >> 4) * 16)) ^ xv;
    const uint32_t vrowo = (uint32_t)vrow * 128;

    // Q fragments (register-resident)
    uint32_t qh[4][4], ql[4][4];
    #pragma unroll
    for (int ks = 0; ks < 4; ks++) {
        uint32_t off = (uint32_t)(w * 16) * 128 + krow + kx[ks];
        LDSM_X4(qh[ks][0], qh[ks][1], qh[ks][2], qh[ks][3], bQh + off);
        LDSM_X4(ql[ks][0], ql[ks][1], ql[ks][2], ql[ks][3], bQl + off);
    }
    __syncthreads();                              // all warps done reading Q
    ld_kv(1, 1); CP_COMMIT();                     // overlays Q region (safe now)

    float oacc[8][4];
    #pragma unroll
    for (int n = 0; n < 8; n++)
        #pragma unroll
        for (int r = 0; r < 4; r++) oacc[n][r] = 0.f;
    float m0r = -1e30f, m1r = -1e30f, l0 = 0.f, l1 = 0.f;

    const int R0 = q0 + w * 16;
    const int r0q = R0 + (lane >> 2);
    const int wklo = max(R0 - WIN, 0);
    const int wkhi = min(R0 + 15 + WIN, SEQ - 1);

    for (int kt = 0; kt < 9; kt++) {
        if (kt) {
            if (kt < 8) CP_WAIT1(); else CP_WAIT0();
            __syncthreads();
        }
        const uint32_t bb = sb + ((kt & 1) ? 0 : AT_BUFSZ);
        const uint32_t bKh = bb, bKl = bb + 8192;
        const uint32_t bVh = bb + 16384, bVl = bb + 24576;
        const int kbase = q0 - WIN + kt * 64;

        // ---- S = Q K^T (skip n16 groups fully outside warp band) ----
        float sc[8][4];
        #pragma unroll
        for (int n = 0; n < 8; n++)
            #pragma unroll
            for (int r = 0; r < 4; r++) sc[n][r] = -1e30f;

        #pragma unroll
        for (int g = 0; g < 4; g++) {
            const int gk0 = kbase + g * 16;
            if (gk0 + 15 < wklo || gk0 > wkhi) continue;
            sc[g * 2 + 0][0] = sc[g * 2 + 0][1] = sc[g * 2 + 0][2] = sc[g * 2 + 0][3] = 0.f;
            sc[g * 2 + 1][0] = sc[g * 2 + 1][1] = sc[g * 2 + 1][2] = sc[g * 2 + 1][3] = 0.f;
            #pragma unroll
            for (int ks = 0; ks < 4; ks++) {
                uint32_t off = (uint32_t)g * 2048 + krow + kx[ks];
                uint32_t h0, h1, h2, h3, e0, e1, e2, e3;
                LDSM_X4(h0, h1, h2, h3, bKh + off);
                LDSM_X4(e0, e1, e2, e3, bKl + off);
                MMA16816(sc[g * 2 + 0], qh[ks], h0, h2);
                MMA16816(sc[g * 2 + 0], qh[ks], e0, e2);
                MMA16816(sc[g * 2 + 0], ql[ks], h0, h2);
                MMA16816(sc[g * 2 + 1], qh[ks], h1, h3);
                MMA16816(sc[g * 2 + 1], qh[ks], e1, e3);
                MMA16816(sc[g * 2 + 1], ql[ks], h1, h3);
            }
        }

        // ---- mask + row max (full-valid fast path) ----
        float mx0 = -1e30f, mx1 = -1e30f;
        #pragma unroll
        for (int g = 0; g < 4; g++) {
            const int gk0 = kbase + g * 16;
            if (gk0 + 15 < wklo || gk0 > wkhi) continue;
            const bool fullv = (gk0 >= R0 + 15 - WIN) && (gk0 + 15 <= R0 + WIN) &&
                               (gk0 >= 0) && (gk0 + 15 < SEQ);
            if (fullv) {
                #pragma unroll
                for (int n = 2 * g; n <= 2 * g + 1; n++) {
                    mx0 = fmaxf(mx0, fmaxf(sc[n][0], sc[n][1]));
                    mx1 = fmaxf(mx1, fmaxf(sc[n][2], sc[n][3]));
                }
            } else {
                #pragma unroll
                for (int n = 2 * g; n <= 2 * g + 1; n++) {
                    const int k0p = kbase + n * 8 + (lane & 3) * 2;
                    const int k1p = k0p + 1;
                    bool v00 = ((unsigned)k0p < SEQ) && (unsigned)(k0p - r0q + WIN) <= 2 * WIN;
                    bool v01 = ((unsigned)k1p < SEQ) && (unsigned)(k1p - r0q + WIN) <= 2 * WIN;
                    bool v10 = ((unsigned)k0p < SEQ) && (unsigned)(k0p - (r0q + 8) + WIN) <= 2 * WIN;
                    bool v11 = ((unsigned)k1p < SEQ) && (unsigned)(k1p - (r0q + 8) + WIN) <= 2 * WIN;
                    if (!v00) sc[n][0] = -1e30f;
                    if (!v01) sc[n][1] = -1e30f;
                    if (!v10) sc[n][2] = -1e30f;
                    if (!v11) sc[n][3] = -1e30f;
                    mx0 = fmaxf(mx0, fmaxf(sc[n][0], sc[n][1]));
                    mx1 = fmaxf(mx1, fmaxf(sc[n][2], sc[n][3]));
                }
            }
        }
        mx0 = fmaxf(mx0, __shfl_xor_sync(0xffffffffu, mx0, 1));
        mx0 = fmaxf(mx0, __shfl_xor_sync(0xffffffffu, mx0, 2));
        mx1 = fmaxf(mx1, __shfl_xor_sync(0xffffffffu, mx1, 1));
        mx1 = fmaxf(mx1, __shfl_xor_sync(0xffffffffu, mx1, 2));

        const float mn0 = fmaxf(m0r, mx0), mn1 = fmaxf(m1r, mx1);
        const float a0 = ex2(m0r - mn0), a1 = ex2(m1r - mn1);
        m0r = mn0; m1r = mn1;

        float s0 = 0.f, s1 = 0.f;
        #pragma unroll
        for (int n = 0; n < 8; n++) {
            sc[n][0] = ex2(sc[n][0] - mn0);
            sc[n][1] = ex2(sc[n][1] - mn0);
            sc[n][2] = ex2(sc[n][2] - mn1);
            sc[n][3] = ex2(sc[n][3] - mn1);
            s0 += sc[n][0] + sc[n][1];
            s1 += sc[n][2] + sc[n][3];
        }
        s0 += __shfl_xor_sync(0xffffffffu, s0, 1);
        s0 += __shfl_xor_sync(0xffffffffu, s0, 2);
        s1 += __shfl_xor_sync(0xffffffffu, s1, 1);
        s1 += __shfl_xor_sync(0xffffffffu, s1, 2);
        l0 = l0 * a0 + s0;
        l1 = l1 * a1 + s1;
        #pragma unroll
        for (int n = 0; n < 8; n++) {
            oacc[n][0] *= a0; oacc[n][1] *= a0;
            oacc[n][2] *= a1; oacc[n][3] *= a1;
        }

        // ---- repack P into A-fragments (hi/lo) ----
        uint32_t ph[4][4], pl[4][4];
        #pragma unroll
        for (int g = 0; g < 4; g++) {
            pack_hl(sc[2 * g][0],     sc[2 * g][1],     ph[g][0], pl[g][0]);
            pack_hl(sc[2 * g][2],     sc[2 * g][3],     ph[g][1], pl[g][1]);
            pack_hl(sc[2 * g + 1][0], sc[2 * g + 1][1], ph[g][2], pl[g][2]);
            pack_hl(sc[2 * g + 1][2], sc[2 * g + 1][3], ph[g][3], pl[g][3]);
        }

        // ---- O += P V (skip key groups fully outside warp band) ----
        #pragma unroll
        for (int g = 0; g < 4; g++) {
            const int gk0 = kbase + g * 16;
            if (gk0 + 15 < wklo || gk0 > wkhi) continue;
            #pragma unroll
            for (int t2 = 0; t2 < 4; t2++) {
                uint32_t voff = (uint32_t)g * 2048 + vrowo + vx[t2];
                uint32_t v0, v1, v2, v3, u0, u1, u2, u3;
                LDSM_X4_T(v0, v1, v2, v3, bVh + voff);
                LDSM_X4_T(u0, u1, u2, u3, bVl + voff);
                MMA16816(oacc[2 * t2 + 0], ph[g], v0, v1);
                MMA16816(oacc[2 * t2 + 0], ph[g], u0, u1);
                MMA16816(oacc[2 * t2 + 0], pl[g], v0, v1);
                MMA16816(oacc[2 * t2 + 1], ph[g], v2, v3);
                MMA16816(oacc[2 * t2 + 1], ph[g], u2, u3);
                MMA16816(oacc[2 * t2 + 1], pl[g], v2, v3);
            }
        }

        __syncthreads();
        if (kt + 2 <= 8) { ld_kv(kt + 2, kt & 1); CP_COMMIT(); }
    }

    // ---- epilogue ----
    const float i0 = 1.f / l0, i1 = 1.f / l1;
    #pragma unroll
    for (int n = 0; n < 8; n++) {
        const int col = cb + n * 8 + (lane & 3) * 2;
        float2 w0, w1;
        w0.x = oacc[n][0] * i0; w0.y = oacc[n][1] * i0;
        w1.x = oacc[n][2] * i1; w1.y = oacc[n][3] * i1;
        *(float2*)(out + (size_t)r0q * HIDDIM + col) = w0;
        *(float2*)(out + (size_t)(r0q + 8) * HIDDIM + col) = w1;
    }
}

// ---------------------------------------------------------------------------
extern "C" void kernel_launch(void* const* d_in, const int* in_sizes, int n_in,
                              void* d_out, int out_size)
{
    const float* X  = (const float*)d_in[0];
    const float* Wq = (const float*)d_in[1];
    const float* bq = (const float*)d_in[2];
    const float* Wk = (const float*)d_in[3];
    const float* bk = (const float*)d_in[4];
    const float* Wv = (const float*)d_in[5];
    const float* bv = (const float*)d_in[6];
    float* out = (float*)d_out;

    void *qh, *ql, *kh, *kl, *vh, *vl, *xh, *xl, *wh, *wl;
    cudaGetSymbolAddress(&qh, g_Qh);  cudaGetSymbolAddress(&ql, g_Ql);
    cudaGetSymbolAddress(&kh, g_Kh);  cudaGetSymbolAddress(&kl, g_Kl);
    cudaGetSymbolAddress(&vh, g_Vh);  cudaGetSymbolAddress(&vl, g_Vl);
    cudaGetSymbolAddress(&xh, g_Xhi); cudaGetSymbolAddress(&xl, g_Xlo);
    cudaGetSymbolAddress(&wh, g_Wthi); cudaGetSymbolAddress(&wl, g_Wtlo);

    __nv_bfloat16* Xhi = (__nv_bfloat16*)xh;
    __nv_bfloat16* Xlo = (__nv_bfloat16*)xl;
    __nv_bfloat16* Whi = (__nv_bfloat16*)wh;
    __nv_bfloat16* Wlo = (__nv_bfloat16*)wl;

    const int n4 = SEQ * HIDDIM / 4;
    convert_x4<<<(n4 + 255) / 256, 256>>>((const float4*)X, (uint2*)Xhi,
                                          (uint2*)Xlo, n4);
    dim3 wtg(HIDDIM / 32, HIDDIM / 32, 3), wtb(32, 8);
    wt_convert3<<<wtg, wtb>>>(Wq, Wk, Wv, Whi, Wlo);

    cudaFuncSetAttribute(gemm_mma_fused,
                         cudaFuncAttributeMaxDynamicSharedMemorySize, GEMM_SMEM);
    const float qscale = 0.125f * 1.4426950408889634f;   // 1/sqrt(64)*log2(e)
    dim3 gg(3 * HIDDIM / 128, SEQ / 128);                // (18, 64)
    gemm_mma_fused<<<gg, 512, GEMM_SMEM>>>(
        Xhi, Xlo, Whi, Wlo, bq, bk, bv,
        (__nv_bfloat16*)qh, (__nv_bfloat16*)ql,
        (__nv_bfloat16*)kh, (__nv_bfloat16*)kl,
        (__nv_bfloat16*)vh, (__nv_bfloat16*)vl, qscale);

    cudaFuncSetAttribute(swa_mma, cudaFuncAttributeMaxDynamicSharedMemorySize,
                         AT_SMEM);
    swa_mma<<<dim3(SEQ / 64, NHEAD), 128, AT_SMEM>>>(
        (const __nv_bfloat16*)qh, (const __nv_bfloat16*)ql,
        (const __nv_bfloat16*)kh, (const __nv_bfloat16*)kl,
        (const __nv_bfloat16*)vh, (const __nv_bfloat16*)vl, out);
}